// round 11
// baseline (speedup 1.0000x reference)
#include <cuda_runtime.h>
#include <cuda_fp16.h>
#include <math.h>
#include <stdint.h>

// Problem constants
#define Bc   4
#define Sc   1024
#define Dc   1024
#define Hc   16
#define DHc  64
#define Fc   4096
#define TOK  4096          // B*S
#define SIXD 6144          // 6*D
#define TOKD ((size_t)TOK * Dc)   // 4M
#define TOKF ((size_t)TOK * Fc)   // 16M

// ---------------- scratch (no allocations allowed) ----------------
__device__ float  g_st[Bc * Dc];
__device__ float  g_ada[Bc * SIXD];
__device__ __half g_wh[(size_t)29 << 20];    // transposed fp16 weights [N][K]
__device__ __half g_wos[4 << 20];            // stacked WoT [1024][4096]
__device__ float  g_weff[4 * Dc * 4];        // WgEff[i][k][j]
__device__ __half g_nxh[TOK * Dc];           // fp16 modulated LN output
__device__ __half g_qkvh[12 * TOK * Dc];     // q,k,v fp16
__device__ __half g_ao4h[4 * TOK * Dc];      // attention outputs fp16
__device__ float  g_gate[TOK * 4];
__device__ __half g_gsc[TOK * 4 * Dc];       // gate-scaled concat [TOK][4096]
__device__ __half g_fusedh[TOK * Dc];        // fp16
__device__ float  g_xmid[TOK * Dc];
__device__ __half g_h16[2 * TOK * Fc];       // h1, h3 fp16 (GEMM half-out)
__device__ __half g_h1h[TOK * Fc];           // fp16 swiglu output

// weight scratch offsets (elements)
#define WQKV 0
#define WO   ((size_t)12 << 20)
#define WFUS ((size_t)16 << 20)
#define W1   ((size_t)17 << 20)
#define W3   ((size_t)21 << 20)
#define W2   ((size_t)25 << 20)

// ---------------- ptx helpers ----------------
__device__ __forceinline__ void mma_f16(float* c, uint32_t a0, uint32_t a1,
                                        uint32_t a2, uint32_t a3,
                                        uint32_t b0, uint32_t b1) {
    asm("mma.sync.aligned.m16n8k16.row.col.f32.f16.f16.f32 "
        "{%0,%1,%2,%3},{%4,%5,%6,%7},{%8,%9},{%0,%1,%2,%3};"
        : "+f"(c[0]), "+f"(c[1]), "+f"(c[2]), "+f"(c[3])
        : "r"(a0), "r"(a1), "r"(a2), "r"(a3), "r"(b0), "r"(b1));
}
__device__ __forceinline__ void ldsm_x4(uint32_t& r0, uint32_t& r1,
                                        uint32_t& r2, uint32_t& r3, uint32_t addr) {
    asm volatile("ldmatrix.sync.aligned.m8n8.x4.shared.b16 {%0,%1,%2,%3}, [%4];"
                 : "=r"(r0), "=r"(r1), "=r"(r2), "=r"(r3) : "r"(addr));
}
__device__ __forceinline__ void cp16s(uint32_t smem, const void* g) {
    asm volatile("cp.async.cg.shared.global [%0], [%1], 16;" :: "r"(smem), "l"(g));
}
__device__ __forceinline__ void cp_commit() {
    asm volatile("cp.async.commit_group;");
}
template <int N>
__device__ __forceinline__ void cp_wait() {
    asm volatile("cp.async.wait_group %0;" :: "n"(N));
}

// ---------------- weight transpose to fp16 [N][K] ----------------
__global__ __launch_bounds__(256) void wtrans_k(const float* __restrict__ in,
                                                __half* __restrict__ out,
                                                int Kd, int Nd) {
    __shared__ float tile[32][33];
    int n0 = blockIdx.x * 32, k0 = blockIdx.y * 32;
    int tx = threadIdx.x & 31, ty = threadIdx.x >> 5;   // 32 x 8
    #pragma unroll
    for (int i = 0; i < 32; i += 8)
        tile[ty + i][tx] = in[(size_t)(k0 + ty + i) * Nd + n0 + tx];
    __syncthreads();
    #pragma unroll
    for (int i = 0; i < 32; i += 8)
        out[(size_t)(n0 + ty + i) * Kd + k0 + tx] = __float2half_rn(tile[tx][ty + i]);
}

struct TP17 { const float* p[17]; };
__global__ __launch_bounds__(256) void wtrans17_k(TP17 tp, __half* __restrict__ out) {
    __shared__ float tile[32][33];
    const float* in = tp.p[blockIdx.z];
    __half* o = out + ((size_t)blockIdx.z << 20);
    int n0 = blockIdx.x * 32, k0 = blockIdx.y * 32;
    int tx = threadIdx.x & 31, ty = threadIdx.x >> 5;
    #pragma unroll
    for (int i = 0; i < 32; i += 8)
        tile[ty + i][tx] = in[(size_t)(k0 + ty + i) * Dc + n0 + tx];
    __syncthreads();
    #pragma unroll
    for (int i = 0; i < 32; i += 8)
        o[(size_t)(n0 + ty + i) * Dc + k0 + tx] = __float2half_rn(tile[tx][ty + i]);
}

// stacked WoT: out[n][i*1024+k] = whWO[i][n][k]   (4M halves)
__global__ __launch_bounds__(256) void wostk_k(const __half* __restrict__ whWO,
                                               __half* __restrict__ out) {
    int idx8 = (blockIdx.x * 256 + threadIdx.x) * 8;   // 4M halves total
    int n = idx8 >> 12;
    int r = idx8 & 4095;
    int i = r >> 10, k = r & 1023;
    uint4 v = *(const uint4*)&whWO[((size_t)i << 20) + n * 1024 + k];
    *(uint4*)&out[(size_t)n * 4096 + r] = v;
}

// WgEff[i][k][j] = sum_n Wo_i[k][n] * wg[(i*1024+n)*4+j]   (warp per (i,k))
struct WoP { const float* p[4]; };
__global__ __launch_bounds__(256) void wgeff_k(WoP wo, const float* __restrict__ wg,
                                               float* __restrict__ weff) {
    int o = blockIdx.x * 8 + (threadIdx.x >> 5);   // 0..4095
    int lane = threadIdx.x & 31;
    int i = o >> 10, k = o & 1023;
    const float* wrow = wo.p[i] + (size_t)k * Dc;
    float4 acc = make_float4(0.f, 0.f, 0.f, 0.f);
    for (int n = lane; n < Dc; n += 32) {
        float wv = wrow[n];
        float4 gv = *(const float4*)&wg[(size_t)(i * Dc + n) * 4];
        acc.x = fmaf(wv, gv.x, acc.x);
        acc.y = fmaf(wv, gv.y, acc.y);
        acc.z = fmaf(wv, gv.z, acc.z);
        acc.w = fmaf(wv, gv.w, acc.w);
    }
    #pragma unroll
    for (int off = 16; off; off >>= 1) {
        acc.x += __shfl_xor_sync(~0u, acc.x, off);
        acc.y += __shfl_xor_sync(~0u, acc.y, off);
        acc.z += __shfl_xor_sync(~0u, acc.z, off);
        acc.w += __shfl_xor_sync(~0u, acc.w, off);
    }
    if (!lane) *(float4*)&weff[(size_t)o * 4] = acc;
}

// ---------------- elementwise helpers ----------------
__global__ void silu_k(const float* __restrict__ in, float* __restrict__ out, int n) {
    int i = blockIdx.x * blockDim.x + threadIdx.x;
    if (i < n) { float v = in[i]; out[i] = v / (1.f + __expf(-v)); }
}

__global__ __launch_bounds__(256) void ada_k(const float* __restrict__ st,
                                             const float* __restrict__ W,
                                             const float* __restrict__ bias,
                                             float* __restrict__ out) {
    int o = blockIdx.x * 8 + (threadIdx.x >> 5);
    int lane = threadIdx.x & 31;
    int b = o / SIXD, n = o - b * SIXD;
    float acc = 0.f;
    for (int k = lane; k < Dc; k += 32)
        acc = fmaf(st[b * Dc + k], W[(size_t)k * SIXD + n], acc);
    #pragma unroll
    for (int off = 16; off; off >>= 1) acc += __shfl_xor_sync(~0u, acc, off);
    if (!lane) out[o] = acc + bias[n];
}

__global__ __launch_bounds__(256) void ln_mod_k(const float* __restrict__ X,
                                                const float* __restrict__ gam,
                                                const float* __restrict__ bet,
                                                const float* __restrict__ ada,
                                                int sh_off, int sc_off,
                                                __half* __restrict__ out) {
    int t = blockIdx.x;
    int b = t >> 10;
    int tid = threadIdx.x;
    const float* xr = X + (size_t)t * Dc;
    float s = 0.f, ss = 0.f;
    for (int i = tid; i < Dc; i += 256) { float v = xr[i]; s += v; ss = fmaf(v, v, ss); }
    __shared__ float r1[8], r2[8];
    __shared__ float muS, rsS;
    #pragma unroll
    for (int off = 16; off; off >>= 1) {
        s  += __shfl_xor_sync(~0u, s,  off);
        ss += __shfl_xor_sync(~0u, ss, off);
    }
    if ((tid & 31) == 0) { r1[tid >> 5] = s; r2[tid >> 5] = ss; }
    __syncthreads();
    if (tid < 32) {
        float a = (tid < 8) ? r1[tid] : 0.f;
        float c = (tid < 8) ? r2[tid] : 0.f;
        #pragma unroll
        for (int off = 4; off; off >>= 1) {
            a += __shfl_xor_sync(~0u, a, off);
            c += __shfl_xor_sync(~0u, c, off);
        }
        if (tid == 0) {
            float mu = a * (1.f / Dc);
            float var = c * (1.f / Dc) - mu * mu;
            muS = mu; rsS = rsqrtf(var + 1e-6f);
        }
    }
    __syncthreads();
    float mu = muS, rs = rsS;
    const float* ar = ada + b * SIXD;
    __half* orow = out + (size_t)t * Dc;
    for (int i = tid; i < Dc; i += 256) {
        float v = (xr[i] - mu) * rs * gam[i] + bet[i];
        orow[i] = __float2half_rn(fmaf(v, 1.f + ar[sc_off + i], ar[sh_off + i]));
    }
}

// ---------------- FP16 TC GEMM: 128x128 tile, ldmatrix + m16n8k16 ----------------
#define RS   40
#define ASZh (128 * RS)
#define STGh (2 * ASZh)
#define NSTG 4
#define STGB (STGh * 2)
#define GEMM_SMEM (NSTG * STGB)      // 81920 B

__global__ __launch_bounds__(256, 2) void gemm_tc(
    const __half* __restrict__ A, size_t azs,
    const __half* __restrict__ Bt, size_t bzs,
    float* __restrict__ C, __half* __restrict__ Ch, size_t czs,
    int M, int N, int K,
    const float* __restrict__ resid, const float* __restrict__ gate) {
    extern __shared__ char smraw[];
    uint32_t smbase = (uint32_t)__cvta_generic_to_shared(smraw);

    A += azs * blockIdx.z; Bt += bzs * blockIdx.z;
    if (Ch) Ch += czs * blockIdx.z; else C += czs * blockIdx.z;

    int tid = threadIdx.x;
    int bx = blockIdx.x, by = blockIdx.y;
    int w = tid >> 5, lane = tid & 31;
    int wm = (w >> 2) * 64, wn = (w & 3) * 32;
    int g = lane >> 2, t = lane & 3;
    int lm = lane & 7, lq = lane >> 3;

    float acc[4][4][4];
    #pragma unroll
    for (int i = 0; i < 4; i++)
        #pragma unroll
        for (int j = 0; j < 4; j++)
            #pragma unroll
            for (int r = 0; r < 4; r++) acc[i][j][r] = 0.f;

    const __half* Ag = A + (size_t)(by * 128) * K;
    const __half* Bg = Bt + (size_t)(bx * 128) * K;

    uint32_t aoff[4], boff[2];
    {
        int koff = (lq >> 1) * 8;
        int rA = lm + 8 * (lq & 1);
        #pragma unroll
        for (int i = 0; i < 4; i++)
            aoff[i] = (uint32_t)(((wm + 16 * i + rA) * RS + koff) * 2);
        #pragma unroll
        for (int jp = 0; jp < 2; jp++)
            boff[jp] = (uint32_t)((ASZh + (wn + 16 * jp + 8 * (lq & 1) + lm) * RS + koff) * 2);
    }

    int r0 = tid >> 2;
    int p8 = (tid & 3) * 8;

    auto load_stage = [&](int st, int k0) {
        uint32_t As = smbase + st * STGB;
        uint32_t Bs = As + ASZh * 2;
        cp16s(As + (r0 * RS + p8) * 2,        Ag + (size_t)r0 * K + k0 + p8);
        cp16s(As + ((r0 + 64) * RS + p8) * 2, Ag + (size_t)(r0 + 64) * K + k0 + p8);
        cp16s(Bs + (r0 * RS + p8) * 2,        Bg + (size_t)r0 * K + k0 + p8);
        cp16s(Bs + ((r0 + 64) * RS + p8) * 2, Bg + (size_t)(r0 + 64) * K + k0 + p8);
    };

    load_stage(0, 0);  cp_commit();
    load_stage(1, 32); cp_commit();
    load_stage(2, 64); cp_commit();
    int cur = 0;
    int nch = K >> 5;

    for (int c = 0; c < nch; c++) {
        cp_wait<2>();
        __syncthreads();
        if (c + 3 < nch) {
            int nst = cur + 3; if (nst >= NSTG) nst -= NSTG;
            load_stage(nst, (c + 3) * 32);
        }
        cp_commit();

        uint32_t stb = smbase + cur * STGB;
        #pragma unroll
        for (int ks = 0; ks < 2; ks++) {
            uint32_t kadd = stb + ks * 32;
            uint32_t af[4][4], bf[4][2];
            #pragma unroll
            for (int i = 0; i < 4; i++)
                ldsm_x4(af[i][0], af[i][1], af[i][2], af[i][3], kadd + aoff[i]);
            #pragma unroll
            for (int jp = 0; jp < 2; jp++)
                ldsm_x4(bf[2 * jp][0], bf[2 * jp + 1][0],
                        bf[2 * jp][1], bf[2 * jp + 1][1], kadd + boff[jp]);
            #pragma unroll
            for (int i = 0; i < 4; i++)
                #pragma unroll
                for (int j = 0; j < 4; j++)
                    mma_f16(acc[i][j], af[i][0], af[i][1], af[i][2], af[i][3],
                            bf[j][0], bf[j][1]);
        }
        cur++; if (cur >= NSTG) cur -= NSTG;
    }

    #pragma unroll
    for (int i = 0; i < 4; i++) {
        #pragma unroll
        for (int j = 0; j < 4; j++) {
            int row0 = by * 128 + wm + 16 * i + g;
            int col  = bx * 128 + wn + 8 * j + 2 * t;
            size_t b0i = (size_t)row0 * N + col;
            size_t b1i = (size_t)(row0 + 8) * N + col;
            if (Ch) {
                *(__half2*)&Ch[b0i] = __floats2half2_rn(acc[i][j][0], acc[i][j][1]);
                *(__half2*)&Ch[b1i] = __floats2half2_rn(acc[i][j][2], acc[i][j][3]);
            } else if (resid == nullptr) {
                *(float2*)&C[b0i] = make_float2(acc[i][j][0], acc[i][j][1]);
                *(float2*)&C[b1i] = make_float2(acc[i][j][2], acc[i][j][3]);
            } else {
                int bb0 = row0 >> 10, bb1 = (row0 + 8) >> 10;
                float2 gr0 = *(const float2*)&gate[(size_t)bb0 * SIXD + col];
                float2 gr1 = *(const float2*)&gate[(size_t)bb1 * SIXD + col];
                float2 rv0 = *(const float2*)&resid[b0i];
                float2 rv1 = *(const float2*)&resid[b1i];
                *(float2*)&C[b0i] = make_float2(fmaf(gr0.x, acc[i][j][0], rv0.x),
                                                fmaf(gr0.y, acc[i][j][1], rv0.y));
                *(float2*)&C[b1i] = make_float2(fmaf(gr1.x, acc[i][j][2], rv1.x),
                                                fmaf(gr1.y, acc[i][j][3], rv1.y));
            }
        }
    }
}

// ---------------- fp16 tensor-core flash attention (full branches) ----------------
#define APH 36
#define ATT_SMEM_BYTES ((128 * APH + 64 * APH + 64 * APH) * 4)   // 36864 B

__global__ __launch_bounds__(256) void attn_tc_k(const __half* __restrict__ Q,
                                                 const __half* __restrict__ Km,
                                                 const __half* __restrict__ Vm,
                                                 __half* __restrict__ O, int branch) {
    extern __shared__ uint32_t smu[];
    uint32_t* Ph = smu;
    uint32_t* Kh = smu + 128 * APH;
    uint32_t* Vt = Kh + 64 * APH;
    int tid = threadIdx.x, lane = tid & 31, w = tid >> 5;
    int g = lane >> 2, t = lane & 3;
    int bh = blockIdx.y;
    int b = bh >> 4, h = bh & 15;
    int qb = blockIdx.x * 128;
    int headoff = h * DHc;

    #pragma unroll
    for (int i = 0; i < 4; i++) {
        int idx = tid + i * 256;
        int row = idx >> 3, q4 = idx & 7;
        uint4 v = *(const uint4*)&Q[((size_t)(b * Sc + qb + row)) * Dc + headoff + q4 * 8];
        *(uint4*)&Ph[row * APH + q4 * 4] = v;
    }
    __syncthreads();

    int r0 = w * 16 + g;
    uint32_t qa[4][4];
    #pragma unroll
    for (int kk = 0; kk < 4; kk++) {
        qa[kk][0] = Ph[r0 * APH + kk * 8 + t];
        qa[kk][1] = Ph[(r0 + 8) * APH + kk * 8 + t];
        qa[kk][2] = Ph[r0 * APH + kk * 8 + t + 4];
        qa[kk][3] = Ph[(r0 + 8) * APH + kk * 8 + t + 4];
    }

    float m0 = -INFINITY, m1 = -INFINITY, l0 = 0.f, l1 = 0.f;
    float o[8][4];
    #pragma unroll
    for (int j = 0; j < 8; j++)
        #pragma unroll
        for (int r = 0; r < 4; r++) o[j][r] = 0.f;

    int qi0 = qb + r0, qi1 = qi0 + 8;

    for (int kt = 0; kt < Sc; kt += 64) {
        __syncthreads();
        #pragma unroll
        for (int i = 0; i < 2; i++) {
            int idx = tid + i * 256;
            int row = idx >> 3, q4 = idx & 7;
            uint4 v = *(const uint4*)&Km[((size_t)(b * Sc + kt + row)) * Dc + headoff + q4 * 8];
            *(uint4*)&Kh[row * APH + q4 * 4] = v;
        }
        {
            int kp = tid & 31, dg = tid >> 5;
            const __half* v0 = &Vm[((size_t)(b * Sc + kt + 2 * kp)) * Dc + headoff + dg * 8];
            uint4 va = *(const uint4*)v0;
            uint4 vb = *(const uint4*)(v0 + Dc);
            const __half* ah = (const __half*)&va;
            const __half* bh2 = (const __half*)&vb;
            #pragma unroll
            for (int j = 0; j < 8; j++) {
                __half2 hv = __halves2half2(ah[j], bh2[j]);
                Vt[(dg * 8 + j) * APH + kp] = *(const uint32_t*)&hv;
            }
        }
        __syncthreads();

        float sc[8][4];
        #pragma unroll
        for (int jn = 0; jn < 8; jn++)
            #pragma unroll
            for (int r = 0; r < 4; r++) sc[jn][r] = 0.f;
        #pragma unroll
        for (int kk = 0; kk < 4; kk++) {
            #pragma unroll
            for (int jn = 0; jn < 8; jn++) {
                uint32_t b0 = Kh[(jn * 8 + g) * APH + kk * 8 + t];
                uint32_t b1 = Kh[(jn * 8 + g) * APH + kk * 8 + t + 4];
                mma_f16(sc[jn], qa[kk][0], qa[kk][1], qa[kk][2], qa[kk][3], b0, b1);
            }
        }

        float rm0 = m0, rm1 = m1;
        #pragma unroll
        for (int jn = 0; jn < 8; jn++) {
            int kj = kt + jn * 8 + 2 * t;
            float b00 = 0.f, b01 = 0.f, b10 = 0.f, b11 = 0.f;
            if (branch == 0) {
                b00 = -(float)abs(qi0 - kj);     b01 = -(float)abs(qi0 - kj - 1);
                b10 = -(float)abs(qi1 - kj);     b11 = -(float)abs(qi1 - kj - 1);
            }
            sc[jn][0] = fmaf(sc[jn][0], 0.125f, b00);
            sc[jn][1] = fmaf(sc[jn][1], 0.125f, b01);
            sc[jn][2] = fmaf(sc[jn][2], 0.125f, b10);
            sc[jn][3] = fmaf(sc[jn][3], 0.125f, b11);
            rm0 = fmaxf(rm0, fmaxf(sc[jn][0], sc[jn][1]));
            rm1 = fmaxf(rm1, fmaxf(sc[jn][2], sc[jn][3]));
        }
        rm0 = fmaxf(rm0, __shfl_xor_sync(~0u, rm0, 1));
        rm0 = fmaxf(rm0, __shfl_xor_sync(~0u, rm0, 2));
        rm1 = fmaxf(rm1, __shfl_xor_sync(~0u, rm1, 1));
        rm1 = fmaxf(rm1, __shfl_xor_sync(~0u, rm1, 2));
        float corr0 = __expf(m0 - rm0), corr1 = __expf(m1 - rm1);
        m0 = rm0; m1 = rm1;

        float sum0 = 0.f, sum1 = 0.f;
        #pragma unroll
        for (int jn = 0; jn < 8; jn++) {
            float p0 = __expf(sc[jn][0] - m0), p1 = __expf(sc[jn][1] - m0);
            float p2 = __expf(sc[jn][2] - m1), p3 = __expf(sc[jn][3] - m1);
            sum0 += p0 + p1; sum1 += p2 + p3;
            __half2 hp0 = __floats2half2_rn(p0, p1);
            __half2 hp1 = __floats2half2_rn(p2, p3);
            Ph[r0 * APH + jn * 4 + t] = *(const uint32_t*)&hp0;
            Ph[(r0 + 8) * APH + jn * 4 + t] = *(const uint32_t*)&hp1;
        }
        sum0 += __shfl_xor_sync(~0u, sum0, 1);
        sum0 += __shfl_xor_sync(~0u, sum0, 2);
        sum1 += __shfl_xor_sync(~0u, sum1, 1);
        sum1 += __shfl_xor_sync(~0u, sum1, 2);
        l0 = fmaf(l0, corr0, sum0);
        l1 = fmaf(l1, corr1, sum1);
        #pragma unroll
        for (int jd = 0; jd < 8; jd++) {
            o[jd][0] *= corr0; o[jd][1] *= corr0;
            o[jd][2] *= corr1; o[jd][3] *= corr1;
        }
        __syncwarp();

        #pragma unroll
        for (int ks = 0; ks < 4; ks++) {
            uint32_t pa0 = Ph[r0 * APH + ks * 8 + t];
            uint32_t pa1 = Ph[(r0 + 8) * APH + ks * 8 + t];
            uint32_t pa2 = Ph[r0 * APH + ks * 8 + t + 4];
            uint32_t pa3 = Ph[(r0 + 8) * APH + ks * 8 + t + 4];
            #pragma unroll
            for (int jd = 0; jd < 8; jd++) {
                uint32_t vb0 = Vt[(jd * 8 + g) * APH + ks * 8 + t];
                uint32_t vb1 = Vt[(jd * 8 + g) * APH + ks * 8 + t + 4];
                mma_f16(o[jd], pa0, pa1, pa2, pa3, vb0, vb1);
            }
        }
    }

    float inv0 = 1.f / l0, inv1 = 1.f / l1;
    size_t row0g = ((size_t)(b * Sc + qb + r0)) * Dc + headoff;
    size_t row1g = row0g + (size_t)8 * Dc;
    #pragma unroll
    for (int jd = 0; jd < 8; jd++) {
        int col = jd * 8 + 2 * t;
        *(__half2*)&O[row0g + col] =
            __floats2half2_rn(o[jd][0] * inv0, o[jd][1] * inv0);
        *(__half2*)&O[row1g + col] =
            __floats2half2_rn(o[jd][2] * inv1, o[jd][3] * inv1);
    }
}

// ---------------- sparse attention for masked branches (fp16 in/out) ----------------
__global__ __launch_bounds__(128) void attn_sparse_k(const __half* __restrict__ Q,
                                                     const __half* __restrict__ Km,
                                                     const __half* __restrict__ Vm,
                                                     __half* __restrict__ O, int mode) {
    int w = threadIdx.x >> 5, lane = threadIdx.x & 31;
    int qi = blockIdx.x * 4 + w;
    int bh = blockIdx.y;
    int b = bh >> 4, h = bh & 15;
    size_t rowbase = ((size_t)(b * Sc + qi)) * Dc + (size_t)h * DHc;
    float q0 = __half2float(Q[rowbase + lane]);
    float q1 = __half2float(Q[rowbase + 32 + lane]);

    int k0i, nk;
    if (mode == 1) {
        k0i = qi - 1; nk = 3;
        if (qi == 0)      { k0i = 0; nk = 2; }
        if (qi == Sc - 1) { nk = 2; }
    } else {
        k0i = qi & ~1; nk = 2;
    }

    float s[3] = {0.f, 0.f, 0.f};
    #pragma unroll 3
    for (int kk = 0; kk < 3; kk++) {
        if (kk < nk) {
            size_t kb = ((size_t)(b * Sc + k0i + kk)) * Dc + (size_t)h * DHc;
            float acc = fmaf(q0, __half2float(Km[kb + lane]),
                             q1 * __half2float(Km[kb + 32 + lane]));
            #pragma unroll
            for (int off = 16; off; off >>= 1)
                acc += __shfl_xor_sync(~0u, acc, off);
            s[kk] = acc * 0.125f;
        }
    }
    float mx = s[0];
    for (int kk = 1; kk < nk; kk++) mx = fmaxf(mx, s[kk]);
    float p[3], l = 0.f;
    for (int kk = 0; kk < nk; kk++) { p[kk] = __expf(s[kk] - mx); l += p[kk]; }
    float inv = 1.f / l;

    float o0 = 0.f, o1 = 0.f;
    #pragma unroll 3
    for (int kk = 0; kk < 3; kk++) {
        if (kk < nk) {
            size_t vb = ((size_t)(b * Sc + k0i + kk)) * Dc + (size_t)h * DHc;
            o0 = fmaf(p[kk], __half2float(Vm[vb + lane]), o0);
            o1 = fmaf(p[kk], __half2float(Vm[vb + 32 + lane]), o1);
        }
    }
    O[rowbase + lane]      = __float2half_rn(o0 * inv);
    O[rowbase + 32 + lane] = __float2half_rn(o1 * inv);
}

// ---------------- gate from attention outputs via WgEff ----------------
// logit_j(t) = sum_{i,k} ao_i[t,k] * WgEff[i][k][j] + bg[j]
__global__ __launch_bounds__(256) void gate2_k(const __half* __restrict__ Ao,
                                               const float* __restrict__ weff,
                                               const float* __restrict__ bg,
                                               float* __restrict__ gate) {
    int t = blockIdx.x, tid = threadIdx.x;
    float4 acc = make_float4(0.f, 0.f, 0.f, 0.f);
    for (int d = tid; d < 4 * Dc; d += 256) {
        int i = d >> 10, k = d & 1023;
        float v = __half2float(Ao[(size_t)i * TOKD + (size_t)t * Dc + k]);
        float4 wv = *(const float4*)&weff[(size_t)d * 4];
        acc.x = fmaf(v, wv.x, acc.x);
        acc.y = fmaf(v, wv.y, acc.y);
        acc.z = fmaf(v, wv.z, acc.z);
        acc.w = fmaf(v, wv.w, acc.w);
    }
    #pragma unroll
    for (int off = 16; off; off >>= 1) {
        acc.x += __shfl_xor_sync(~0u, acc.x, off);
        acc.y += __shfl_xor_sync(~0u, acc.y, off);
        acc.z += __shfl_xor_sync(~0u, acc.z, off);
        acc.w += __shfl_xor_sync(~0u, acc.w, off);
    }
    __shared__ float4 red[8];
    if ((tid & 31) == 0) red[tid >> 5] = acc;
    __syncthreads();
    if (tid == 0) {
        float4 a = red[0];
        #pragma unroll
        for (int i = 1; i < 8; i++) {
            a.x += red[i].x; a.y += red[i].y; a.z += red[i].z; a.w += red[i].w;
        }
        float l0 = a.x + bg[0], l1 = a.y + bg[1], l2 = a.z + bg[2], l3 = a.w + bg[3];
        float mx = fmaxf(fmaxf(l0, l1), fmaxf(l2, l3));
        float e0 = __expf(l0 - mx), e1 = __expf(l1 - mx),
              e2 = __expf(l2 - mx), e3 = __expf(l3 - mx);
        float inv = 1.f / (e0 + e1 + e2 + e3);
        gate[t * 4 + 0] = e0 * inv; gate[t * 4 + 1] = e1 * inv;
        gate[t * 4 + 2] = e2 * inv; gate[t * 4 + 3] = e3 * inv;
    }
}

// gsc[t][i*1024+k] = fp16( g_i(t) * ao_i[t,k] )
__global__ __launch_bounds__(256) void scalecat_k(const __half* __restrict__ Ao,
                                                  const float* __restrict__ gate,
                                                  __half* __restrict__ out) {
    size_t idx4 = ((size_t)blockIdx.x * 256 + threadIdx.x) * 4;   // TOK*4096 total
    int t = (int)(idx4 >> 12);
    int d = (int)(idx4 & 4095);
    int i = d >> 10, k = d & 1023;
    float gi = gate[t * 4 + i];
    const __half* src = &Ao[(size_t)i * TOKD + (size_t)t * Dc + k];
    uint2 raw = *(const uint2*)src;
    const __half* hv = (const __half*)&raw;
    __half2 o0 = __floats2half2_rn(gi * __half2float(hv[0]), gi * __half2float(hv[1]));
    __half2 o1 = __floats2half2_rn(gi * __half2float(hv[2]), gi * __half2float(hv[3]));
    uint2 ov;
    ((__half2*)&ov)[0] = o0;
    ((__half2*)&ov)[1] = o1;
    *(uint2*)&out[idx4] = ov;
}

__global__ void swiglu_k(const __half* __restrict__ h1,
                         const __half* __restrict__ h3,
                         __half* __restrict__ out, size_t n) {
    size_t i = (size_t)blockIdx.x * 256 + threadIdx.x;
    if (i < n) {
        float a = __half2float(h1[i]);
        out[i] = __float2half_rn((a / (1.f + __expf(-a))) * __half2float(h3[i]));
    }
}

// ---------------- host launch ----------------
extern "C" void kernel_launch(void* const* d_in, const int* in_sizes, int n_in,
                              void* d_out, int out_size) {
    const float* x      = (const float*)d_in[0];
    const float* t_emb  = (const float*)d_in[1];
    const float* ln1_g  = (const float*)d_in[2];
    const float* ln1_b  = (const float*)d_in[3];
    const float* ln2_g  = (const float*)d_in[4];
    const float* ln2_b  = (const float*)d_in[5];
    const float* ada_w  = (const float*)d_in[6];
    const float* ada_b  = (const float*)d_in[7];

    const float *fus_wg, *fus_bg, *fus_wo, *ffn_w1, *ffn_w2, *ffn_w3;
    int ab;
    if (in_sizes[8] == 16384) {
        fus_wg = (const float*)d_in[8];  fus_bg = (const float*)d_in[9];
        fus_wo = (const float*)d_in[10];
        ffn_w1 = (const float*)d_in[11]; ffn_w2 = (const float*)d_in[12];
        ffn_w3 = (const float*)d_in[13];
        ab = 14;
    } else {
        ab = 8;
        fus_wg = (const float*)d_in[24]; fus_bg = (const float*)d_in[25];
        fus_wo = (const float*)d_in[26];
        ffn_w1 = (const float*)d_in[27]; ffn_w2 = (const float*)d_in[28];
        ffn_w3 = (const float*)d_in[29];
    }

    float  *st, *ada, *gate, *xmid, *weff;
    __half *wh, *wos, *nxh, *qkvh, *ao4h, *gsc, *fusedh, *h16, *h1h;
    cudaGetSymbolAddress((void**)&st,     g_st);
    cudaGetSymbolAddress((void**)&ada,    g_ada);
    cudaGetSymbolAddress((void**)&wh,     g_wh);
    cudaGetSymbolAddress((void**)&wos,    g_wos);
    cudaGetSymbolAddress((void**)&weff,   g_weff);
    cudaGetSymbolAddress((void**)&nxh,    g_nxh);
    cudaGetSymbolAddress((void**)&qkvh,   g_qkvh);
    cudaGetSymbolAddress((void**)&ao4h,   g_ao4h);
    cudaGetSymbolAddress((void**)&gate,   g_gate);
    cudaGetSymbolAddress((void**)&gsc,    g_gsc);
    cudaGetSymbolAddress((void**)&fusedh, g_fusedh);
    cudaGetSymbolAddress((void**)&xmid,   g_xmid);
    cudaGetSymbolAddress((void**)&h16,    g_h16);
    cudaGetSymbolAddress((void**)&h1h,    g_h1h);
    __half* h1 = h16;
    __half* h3 = h16 + TOKF;

    cudaFuncSetAttribute(attn_tc_k, cudaFuncAttributeMaxDynamicSharedMemorySize,
                         ATT_SMEM_BYTES);
    cudaFuncSetAttribute(gemm_tc, cudaFuncAttributeMaxDynamicSharedMemorySize,
                         GEMM_SMEM);

    float* out = (float*)d_out;

    // 0. weight prep: transpose to fp16 [N][K]; stacked WoT; WgEff
    TP17 tp;
    WoP wop;
    for (int p = 0; p < 4; p++) {
        tp.p[p * 3 + 0] = (const float*)d_in[ab + p * 4 + 0];
        tp.p[p * 3 + 1] = (const float*)d_in[ab + p * 4 + 1];
        tp.p[p * 3 + 2] = (const float*)d_in[ab + p * 4 + 2];
        tp.p[12 + p]    = (const float*)d_in[ab + p * 4 + 3];
        wop.p[p]        = (const float*)d_in[ab + p * 4 + 3];
    }
    tp.p[16] = fus_wo;
    wtrans17_k<<<dim3(32, 32, 17), 256>>>(tp, wh);
    wtrans_k<<<dim3(128, 32), 256>>>(ffn_w1, wh + W1, Dc, Fc);
    wtrans_k<<<dim3(128, 32), 256>>>(ffn_w3, wh + W3, Dc, Fc);
    wtrans_k<<<dim3(32, 128), 256>>>(ffn_w2, wh + W2, Fc, Dc);
    wostk_k<<<(4 << 20) / 2048, 256>>>(wh + WO, wos);
    wgeff_k<<<512, 256>>>(wop, fus_wg, weff);

    // 1. AdaLN parameters
    silu_k<<<(Bc * Dc + 255) / 256, 256>>>(t_emb, st, Bc * Dc);
    ada_k<<<(Bc * SIXD) / 8, 256>>>(st, ada_w, ada_b, ada);

    // 2. nx = modulated LN(x), fp16
    ln_mod_k<<<TOK, 256>>>(x, ln1_g, ln1_b, ada, 0, Dc, nxh);

    // 3. all 12 QKV projections, fp16 output
    dim3 gQKV(Dc / 128, TOK / 128, 12);
    gemm_tc<<<gQKV, 256, GEMM_SMEM>>>(nxh, 0, wh + WQKV, (size_t)1 << 20,
                                      nullptr, qkvh, TOKD, TOK, Dc, Dc,
                                      nullptr, nullptr);

    // 4. four attention branches (fp16 in/out)
    dim3 gAttn(Sc / 128, Bc * Hc);
    dim3 gSparse(Sc / 4, Bc * Hc);
    for (int p = 0; p < 4; p++) {
        const __half* q = qkvh + (size_t)(3 * p + 0) * TOKD;
        const __half* k = qkvh + (size_t)(3 * p + 1) * TOKD;
        const __half* v = qkvh + (size_t)(3 * p + 2) * TOKD;
        __half* ao = ao4h + (size_t)p * TOKD;
        if (p == 1 || p == 2)
            attn_sparse_k<<<gSparse, 128>>>(q, k, v, ao, p);
        else
            attn_tc_k<<<gAttn, 256, ATT_SMEM_BYTES>>>(q, k, v, ao, p);
    }

    // 5. gate directly from attention outputs; scale+concat; one K=4096 GEMM
    gate2_k<<<TOK, 256>>>(ao4h, weff, fus_bg, gate);
    scalecat_k<<<(TOK * 4 * Dc) / 1024, 256>>>(ao4h, gate, gsc);
    dim3 gFuse(Dc / 128, TOK / 128, 1);
    gemm_tc<<<gFuse, 256, GEMM_SMEM>>>(gsc, 0, wos, 0,
                                       nullptr, fusedh, 0, TOK, Dc, 4 * Dc,
                                       nullptr, nullptr);

    // 6. fus_wo projection + first residual (g_m at 2D)
    dim3 gProj(Dc / 128, TOK / 128, 1);
    gemm_tc<<<gProj, 256, GEMM_SMEM>>>(fusedh, 0, wh + WFUS, 0, xmid, nullptr, 0,
                                       TOK, Dc, Dc, x, ada + 2 * Dc);

    // 7. FFN with AdaLN (fp16 intermediate)
    ln_mod_k<<<TOK, 256>>>(xmid, ln2_g, ln2_b, ada, 3 * Dc, 4 * Dc, nxh);
    dim3 gFfnUp(Fc / 128, TOK / 128, 2);
    gemm_tc<<<gFfnUp, 256, GEMM_SMEM>>>(nxh, 0, wh + W1, W3 - W1,
                                        nullptr, h16, TOKF, TOK, Fc, Dc,
                                        nullptr, nullptr);
    size_t nf = TOKF;
    swiglu_k<<<(unsigned)((nf + 255) / 256), 256>>>(h1, h3, h1h, nf);
    gemm_tc<<<gProj, 256, GEMM_SMEM>>>(h1h, 0, wh + W2, 0, out, nullptr, 0,
                                       TOK, Dc, Fc, xmid, ada + 5 * Dc);
}

// round 12
// speedup vs baseline: 1.0161x; 1.0161x over previous
#include <cuda_runtime.h>
#include <cuda_fp16.h>
#include <math.h>
#include <stdint.h>

// Problem constants
#define Bc   4
#define Sc   1024
#define Dc   1024
#define Hc   16
#define DHc  64
#define Fc   4096
#define TOK  4096          // B*S
#define SIXD 6144          // 6*D
#define TOKD ((size_t)TOK * Dc)   // 4M
#define TOKF ((size_t)TOK * Fc)   // 16M

// ---------------- scratch (no allocations allowed) ----------------
__device__ float  g_st[Bc * Dc];
__device__ float  g_ada[Bc * SIXD];
__device__ __half g_wh[(size_t)29 << 20];    // transposed fp16 weights [N][K]
__device__ __half g_wos[4 << 20];            // stacked WoT [1024][4096]
__device__ __half g_wud[8 << 20];            // interleaved FFN-up wt [8192][1024]
__device__ float  g_weff[4 * Dc * 4];        // WgEff[i][k][j]
__device__ __half g_nxh[TOK * Dc];           // fp16 modulated LN output
__device__ __half g_qkvh[12 * TOK * Dc];     // q,k,v fp16
__device__ __half g_ao4h[4 * TOK * Dc];      // attention outputs fp16
__device__ __half g_gsc[TOK * 4 * Dc];       // gate-scaled concat [TOK][4096]
__device__ __half g_fusedh[TOK * Dc];        // fp16
__device__ float  g_xmid[TOK * Dc];
__device__ __half g_h1h[TOK * Fc];           // fp16 swiglu output (fused epilogue)

// weight scratch offsets (elements)
#define WQKV 0
#define WO   ((size_t)12 << 20)
#define WFUS ((size_t)16 << 20)
#define W1   ((size_t)17 << 20)
#define W3   ((size_t)21 << 20)
#define W2   ((size_t)25 << 20)

// ---------------- ptx helpers ----------------
__device__ __forceinline__ void mma_f16(float* c, uint32_t a0, uint32_t a1,
                                        uint32_t a2, uint32_t a3,
                                        uint32_t b0, uint32_t b1) {
    asm("mma.sync.aligned.m16n8k16.row.col.f32.f16.f16.f32 "
        "{%0,%1,%2,%3},{%4,%5,%6,%7},{%8,%9},{%0,%1,%2,%3};"
        : "+f"(c[0]), "+f"(c[1]), "+f"(c[2]), "+f"(c[3])
        : "r"(a0), "r"(a1), "r"(a2), "r"(a3), "r"(b0), "r"(b1));
}
__device__ __forceinline__ void ldsm_x4(uint32_t& r0, uint32_t& r1,
                                        uint32_t& r2, uint32_t& r3, uint32_t addr) {
    asm volatile("ldmatrix.sync.aligned.m8n8.x4.shared.b16 {%0,%1,%2,%3}, [%4];"
                 : "=r"(r0), "=r"(r1), "=r"(r2), "=r"(r3) : "r"(addr));
}
__device__ __forceinline__ void cp16s(uint32_t smem, const void* g) {
    asm volatile("cp.async.cg.shared.global [%0], [%1], 16;" :: "r"(smem), "l"(g));
}
__device__ __forceinline__ void cp_commit() {
    asm volatile("cp.async.commit_group;");
}
template <int N>
__device__ __forceinline__ void cp_wait() {
    asm volatile("cp.async.wait_group %0;" :: "n"(N));
}

// ---------------- weight prep ----------------
__global__ __launch_bounds__(256) void wtrans_k(const float* __restrict__ in,
                                                __half* __restrict__ out,
                                                int Kd, int Nd) {
    __shared__ float tile[32][33];
    int n0 = blockIdx.x * 32, k0 = blockIdx.y * 32;
    int tx = threadIdx.x & 31, ty = threadIdx.x >> 5;
    #pragma unroll
    for (int i = 0; i < 32; i += 8)
        tile[ty + i][tx] = in[(size_t)(k0 + ty + i) * Nd + n0 + tx];
    __syncthreads();
    #pragma unroll
    for (int i = 0; i < 32; i += 8)
        out[(size_t)(n0 + ty + i) * Kd + k0 + tx] = __float2half_rn(tile[tx][ty + i]);
}

struct TP17 { const float* p[17]; };
__global__ __launch_bounds__(256) void wtrans17_k(TP17 tp, __half* __restrict__ out) {
    __shared__ float tile[32][33];
    const float* in = tp.p[blockIdx.z];
    __half* o = out + ((size_t)blockIdx.z << 20);
    int n0 = blockIdx.x * 32, k0 = blockIdx.y * 32;
    int tx = threadIdx.x & 31, ty = threadIdx.x >> 5;
    #pragma unroll
    for (int i = 0; i < 32; i += 8)
        tile[ty + i][tx] = in[(size_t)(k0 + ty + i) * Dc + n0 + tx];
    __syncthreads();
    #pragma unroll
    for (int i = 0; i < 32; i += 8)
        o[(size_t)(n0 + ty + i) * Dc + k0 + tx] = __float2half_rn(tile[tx][ty + i]);
}

// stacked WoT: out[n][i*1024+k] = whWO[i][n][k]
__global__ __launch_bounds__(256) void wostk_k(const __half* __restrict__ whWO,
                                               __half* __restrict__ out) {
    int idx8 = (blockIdx.x * 256 + threadIdx.x) * 8;
    int n = idx8 >> 12;
    int r = idx8 & 4095;
    int i = r >> 10, k = r & 1023;
    uint4 v = *(const uint4*)&whWO[((size_t)i << 20) + n * 1024 + k];
    *(uint4*)&out[(size_t)n * 4096 + r] = v;
}

// interleaved FFN-up weight: row 2c = w1T[c], row 2c+1 = w3T[c]
__global__ __launch_bounds__(256) void wudstk_k(const __half* __restrict__ wh,
                                                __half* __restrict__ out) {
    size_t idx8 = ((size_t)blockIdx.x * 256 + threadIdx.x) * 8;   // 8M halves
    int n = (int)(idx8 >> 10);
    int k = (int)(idx8 & 1023);
    int c = n >> 1, o = n & 1;
    const __half* src = wh + (o ? W3 : W1) + (size_t)c * 1024 + k;
    *(uint4*)&out[(size_t)n * 1024 + k] = *(const uint4*)src;
}

// WgEff[i][k][j] = sum_n Wo_i[k][n] * wg[(i*1024+n)*4+j]
struct WoP { const float* p[4]; };
__global__ __launch_bounds__(256) void wgeff_k(WoP wo, const float* __restrict__ wg,
                                               float* __restrict__ weff) {
    int o = blockIdx.x * 8 + (threadIdx.x >> 5);
    int lane = threadIdx.x & 31;
    int i = o >> 10, k = o & 1023;
    const float* wrow = wo.p[i] + (size_t)k * Dc;
    float4 acc = make_float4(0.f, 0.f, 0.f, 0.f);
    for (int n = lane; n < Dc; n += 32) {
        float wv = wrow[n];
        float4 gv = *(const float4*)&wg[(size_t)(i * Dc + n) * 4];
        acc.x = fmaf(wv, gv.x, acc.x);
        acc.y = fmaf(wv, gv.y, acc.y);
        acc.z = fmaf(wv, gv.z, acc.z);
        acc.w = fmaf(wv, gv.w, acc.w);
    }
    #pragma unroll
    for (int off = 16; off; off >>= 1) {
        acc.x += __shfl_xor_sync(~0u, acc.x, off);
        acc.y += __shfl_xor_sync(~0u, acc.y, off);
        acc.z += __shfl_xor_sync(~0u, acc.z, off);
        acc.w += __shfl_xor_sync(~0u, acc.w, off);
    }
    if (!lane) *(float4*)&weff[(size_t)o * 4] = acc;
}

// ---------------- elementwise helpers ----------------
__global__ void silu_k(const float* __restrict__ in, float* __restrict__ out, int n) {
    int i = blockIdx.x * blockDim.x + threadIdx.x;
    if (i < n) { float v = in[i]; out[i] = v / (1.f + __expf(-v)); }
}

__global__ __launch_bounds__(256) void ada_k(const float* __restrict__ st,
                                             const float* __restrict__ W,
                                             const float* __restrict__ bias,
                                             float* __restrict__ out) {
    int o = blockIdx.x * 8 + (threadIdx.x >> 5);
    int lane = threadIdx.x & 31;
    int b = o / SIXD, n = o - b * SIXD;
    float acc = 0.f;
    for (int k = lane; k < Dc; k += 32)
        acc = fmaf(st[b * Dc + k], W[(size_t)k * SIXD + n], acc);
    #pragma unroll
    for (int off = 16; off; off >>= 1) acc += __shfl_xor_sync(~0u, acc, off);
    if (!lane) out[o] = acc + bias[n];
}

__global__ __launch_bounds__(256) void ln_mod_k(const float* __restrict__ X,
                                                const float* __restrict__ gam,
                                                const float* __restrict__ bet,
                                                const float* __restrict__ ada,
                                                int sh_off, int sc_off,
                                                __half* __restrict__ out) {
    int t = blockIdx.x;
    int b = t >> 10;
    int tid = threadIdx.x;
    const float* xr = X + (size_t)t * Dc;
    float s = 0.f, ss = 0.f;
    for (int i = tid; i < Dc; i += 256) { float v = xr[i]; s += v; ss = fmaf(v, v, ss); }
    __shared__ float r1[8], r2[8];
    __shared__ float muS, rsS;
    #pragma unroll
    for (int off = 16; off; off >>= 1) {
        s  += __shfl_xor_sync(~0u, s,  off);
        ss += __shfl_xor_sync(~0u, ss, off);
    }
    if ((tid & 31) == 0) { r1[tid >> 5] = s; r2[tid >> 5] = ss; }
    __syncthreads();
    if (tid < 32) {
        float a = (tid < 8) ? r1[tid] : 0.f;
        float c = (tid < 8) ? r2[tid] : 0.f;
        #pragma unroll
        for (int off = 4; off; off >>= 1) {
            a += __shfl_xor_sync(~0u, a, off);
            c += __shfl_xor_sync(~0u, c, off);
        }
        if (tid == 0) {
            float mu = a * (1.f / Dc);
            float var = c * (1.f / Dc) - mu * mu;
            muS = mu; rsS = rsqrtf(var + 1e-6f);
        }
    }
    __syncthreads();
    float mu = muS, rs = rsS;
    const float* ar = ada + b * SIXD;
    __half* orow = out + (size_t)t * Dc;
    for (int i = tid; i < Dc; i += 256) {
        float v = (xr[i] - mu) * rs * gam[i] + bet[i];
        orow[i] = __float2half_rn(fmaf(v, 1.f + ar[sc_off + i], ar[sh_off + i]));
    }
}

// ---------------- FP16 TC GEMM: 128x128 tile, ldmatrix + m16n8k16 ----------------
// swiglu=1: N logical (interleaved h1/h3 cols); writes fp16 silu(h1)*h3 at stride N/2.
#define RS   40
#define ASZh (128 * RS)
#define STGh (2 * ASZh)
#define NSTG 4
#define STGB (STGh * 2)
#define GEMM_SMEM (NSTG * STGB)      // 81920 B

__global__ __launch_bounds__(256, 2) void gemm_tc(
    const __half* __restrict__ A, size_t azs,
    const __half* __restrict__ Bt, size_t bzs,
    float* __restrict__ C, __half* __restrict__ Ch, size_t czs,
    int M, int N, int K,
    const float* __restrict__ resid, const float* __restrict__ gate,
    int swiglu) {
    extern __shared__ char smraw[];
    uint32_t smbase = (uint32_t)__cvta_generic_to_shared(smraw);

    A += azs * blockIdx.z; Bt += bzs * blockIdx.z;
    if (Ch) Ch += czs * blockIdx.z; else C += czs * blockIdx.z;

    int tid = threadIdx.x;
    int bx = blockIdx.x, by = blockIdx.y;
    int w = tid >> 5, lane = tid & 31;
    int wm = (w >> 2) * 64, wn = (w & 3) * 32;
    int g = lane >> 2, t = lane & 3;
    int lm = lane & 7, lq = lane >> 3;

    float acc[4][4][4];
    #pragma unroll
    for (int i = 0; i < 4; i++)
        #pragma unroll
        for (int j = 0; j < 4; j++)
            #pragma unroll
            for (int r = 0; r < 4; r++) acc[i][j][r] = 0.f;

    const __half* Ag = A + (size_t)(by * 128) * K;
    const __half* Bg = Bt + (size_t)(bx * 128) * K;

    uint32_t aoff[4], boff[2];
    {
        int koff = (lq >> 1) * 8;
        int rA = lm + 8 * (lq & 1);
        #pragma unroll
        for (int i = 0; i < 4; i++)
            aoff[i] = (uint32_t)(((wm + 16 * i + rA) * RS + koff) * 2);
        #pragma unroll
        for (int jp = 0; jp < 2; jp++)
            boff[jp] = (uint32_t)((ASZh + (wn + 16 * jp + 8 * (lq & 1) + lm) * RS + koff) * 2);
    }

    int r0 = tid >> 2;
    int p8 = (tid & 3) * 8;

    auto load_stage = [&](int st, int k0) {
        uint32_t As = smbase + st * STGB;
        uint32_t Bs = As + ASZh * 2;
        cp16s(As + (r0 * RS + p8) * 2,        Ag + (size_t)r0 * K + k0 + p8);
        cp16s(As + ((r0 + 64) * RS + p8) * 2, Ag + (size_t)(r0 + 64) * K + k0 + p8);
        cp16s(Bs + (r0 * RS + p8) * 2,        Bg + (size_t)r0 * K + k0 + p8);
        cp16s(Bs + ((r0 + 64) * RS + p8) * 2, Bg + (size_t)(r0 + 64) * K + k0 + p8);
    };

    load_stage(0, 0);  cp_commit();
    load_stage(1, 32); cp_commit();
    load_stage(2, 64); cp_commit();
    int cur = 0;
    int nch = K >> 5;

    for (int c = 0; c < nch; c++) {
        cp_wait<2>();
        __syncthreads();
        if (c + 3 < nch) {
            int nst = cur + 3; if (nst >= NSTG) nst -= NSTG;
            load_stage(nst, (c + 3) * 32);
        }
        cp_commit();

        uint32_t stb = smbase + cur * STGB;
        #pragma unroll
        for (int ks = 0; ks < 2; ks++) {
            uint32_t kadd = stb + ks * 32;
            uint32_t af[4][4], bf[4][2];
            #pragma unroll
            for (int i = 0; i < 4; i++)
                ldsm_x4(af[i][0], af[i][1], af[i][2], af[i][3], kadd + aoff[i]);
            #pragma unroll
            for (int jp = 0; jp < 2; jp++)
                ldsm_x4(bf[2 * jp][0], bf[2 * jp + 1][0],
                        bf[2 * jp][1], bf[2 * jp + 1][1], kadd + boff[jp]);
            #pragma unroll
            for (int i = 0; i < 4; i++)
                #pragma unroll
                for (int j = 0; j < 4; j++)
                    mma_f16(acc[i][j], af[i][0], af[i][1], af[i][2], af[i][3],
                            bf[j][0], bf[j][1]);
        }
        cur++; if (cur >= NSTG) cur -= NSTG;
    }

    #pragma unroll
    for (int i = 0; i < 4; i++) {
        #pragma unroll
        for (int j = 0; j < 4; j++) {
            int row0 = by * 128 + wm + 16 * i + g;
            int col  = bx * 128 + wn + 8 * j + 2 * t;
            if (swiglu) {
                int halfN = N >> 1;
                int outc = col >> 1;      // col even: (h1, h3) pair
                float a0 = acc[i][j][0], b0v = acc[i][j][1];
                float a1 = acc[i][j][2], b1v = acc[i][j][3];
                float s0 = (a0 / (1.f + __expf(-a0))) * b0v;
                float s1 = (a1 / (1.f + __expf(-a1))) * b1v;
                Ch[(size_t)row0 * halfN + outc]       = __float2half_rn(s0);
                Ch[(size_t)(row0 + 8) * halfN + outc] = __float2half_rn(s1);
                continue;
            }
            size_t b0i = (size_t)row0 * N + col;
            size_t b1i = (size_t)(row0 + 8) * N + col;
            if (Ch) {
                *(__half2*)&Ch[b0i] = __floats2half2_rn(acc[i][j][0], acc[i][j][1]);
                *(__half2*)&Ch[b1i] = __floats2half2_rn(acc[i][j][2], acc[i][j][3]);
            } else if (resid == nullptr) {
                *(float2*)&C[b0i] = make_float2(acc[i][j][0], acc[i][j][1]);
                *(float2*)&C[b1i] = make_float2(acc[i][j][2], acc[i][j][3]);
            } else {
                int bb0 = row0 >> 10, bb1 = (row0 + 8) >> 10;
                float2 gr0 = *(const float2*)&gate[(size_t)bb0 * SIXD + col];
                float2 gr1 = *(const float2*)&gate[(size_t)bb1 * SIXD + col];
                float2 rv0 = *(const float2*)&resid[b0i];
                float2 rv1 = *(const float2*)&resid[b1i];
                *(float2*)&C[b0i] = make_float2(fmaf(gr0.x, acc[i][j][0], rv0.x),
                                                fmaf(gr0.y, acc[i][j][1], rv0.y));
                *(float2*)&C[b1i] = make_float2(fmaf(gr1.x, acc[i][j][2], rv1.x),
                                                fmaf(gr1.y, acc[i][j][3], rv1.y));
            }
        }
    }
}

// ---------------- fp16 tensor-core flash attention (full branches) ----------------
#define APH 36
#define ATT_SMEM_BYTES ((128 * APH + 64 * APH + 64 * APH) * 4)   // 36864 B

__global__ __launch_bounds__(256) void attn_tc_k(const __half* __restrict__ Q,
                                                 const __half* __restrict__ Km,
                                                 const __half* __restrict__ Vm,
                                                 __half* __restrict__ O, int branch) {
    extern __shared__ uint32_t smu[];
    uint32_t* Ph = smu;
    uint32_t* Kh = smu + 128 * APH;
    uint32_t* Vt = Kh + 64 * APH;
    int tid = threadIdx.x, lane = tid & 31, w = tid >> 5;
    int g = lane >> 2, t = lane & 3;
    int bh = blockIdx.y;
    int b = bh >> 4, h = bh & 15;
    int qb = blockIdx.x * 128;
    int headoff = h * DHc;

    #pragma unroll
    for (int i = 0; i < 4; i++) {
        int idx = tid + i * 256;
        int row = idx >> 3, q4 = idx & 7;
        uint4 v = *(const uint4*)&Q[((size_t)(b * Sc + qb + row)) * Dc + headoff + q4 * 8];
        *(uint4*)&Ph[row * APH + q4 * 4] = v;
    }
    __syncthreads();

    int r0 = w * 16 + g;
    uint32_t qa[4][4];
    #pragma unroll
    for (int kk = 0; kk < 4; kk++) {
        qa[kk][0] = Ph[r0 * APH + kk * 8 + t];
        qa[kk][1] = Ph[(r0 + 8) * APH + kk * 8 + t];
        qa[kk][2] = Ph[r0 * APH + kk * 8 + t + 4];
        qa[kk][3] = Ph[(r0 + 8) * APH + kk * 8 + t + 4];
    }

    float m0 = -INFINITY, m1 = -INFINITY, l0 = 0.f, l1 = 0.f;
    float o[8][4];
    #pragma unroll
    for (int j = 0; j < 8; j++)
        #pragma unroll
        for (int r = 0; r < 4; r++) o[j][r] = 0.f;

    int qi0 = qb + r0, qi1 = qi0 + 8;

    for (int kt = 0; kt < Sc; kt += 64) {
        __syncthreads();
        #pragma unroll
        for (int i = 0; i < 2; i++) {
            int idx = tid + i * 256;
            int row = idx >> 3, q4 = idx & 7;
            uint4 v = *(const uint4*)&Km[((size_t)(b * Sc + kt + row)) * Dc + headoff + q4 * 8];
            *(uint4*)&Kh[row * APH + q4 * 4] = v;
        }
        {
            int kp = tid & 31, dg = tid >> 5;
            const __half* v0 = &Vm[((size_t)(b * Sc + kt + 2 * kp)) * Dc + headoff + dg * 8];
            uint4 va = *(const uint4*)v0;
            uint4 vb = *(const uint4*)(v0 + Dc);
            const __half* ah = (const __half*)&va;
            const __half* bh2 = (const __half*)&vb;
            #pragma unroll
            for (int j = 0; j < 8; j++) {
                __half2 hv = __halves2half2(ah[j], bh2[j]);
                Vt[(dg * 8 + j) * APH + kp] = *(const uint32_t*)&hv;
            }
        }
        __syncthreads();

        float sc[8][4];
        #pragma unroll
        for (int jn = 0; jn < 8; jn++)
            #pragma unroll
            for (int r = 0; r < 4; r++) sc[jn][r] = 0.f;
        #pragma unroll
        for (int kk = 0; kk < 4; kk++) {
            #pragma unroll
            for (int jn = 0; jn < 8; jn++) {
                uint32_t b0 = Kh[(jn * 8 + g) * APH + kk * 8 + t];
                uint32_t b1 = Kh[(jn * 8 + g) * APH + kk * 8 + t + 4];
                mma_f16(sc[jn], qa[kk][0], qa[kk][1], qa[kk][2], qa[kk][3], b0, b1);
            }
        }

        float rm0 = m0, rm1 = m1;
        #pragma unroll
        for (int jn = 0; jn < 8; jn++) {
            int kj = kt + jn * 8 + 2 * t;
            float b00 = 0.f, b01 = 0.f, b10 = 0.f, b11 = 0.f;
            if (branch == 0) {
                b00 = -(float)abs(qi0 - kj);     b01 = -(float)abs(qi0 - kj - 1);
                b10 = -(float)abs(qi1 - kj);     b11 = -(float)abs(qi1 - kj - 1);
            }
            sc[jn][0] = fmaf(sc[jn][0], 0.125f, b00);
            sc[jn][1] = fmaf(sc[jn][1], 0.125f, b01);
            sc[jn][2] = fmaf(sc[jn][2], 0.125f, b10);
            sc[jn][3] = fmaf(sc[jn][3], 0.125f, b11);
            rm0 = fmaxf(rm0, fmaxf(sc[jn][0], sc[jn][1]));
            rm1 = fmaxf(rm1, fmaxf(sc[jn][2], sc[jn][3]));
        }
        rm0 = fmaxf(rm0, __shfl_xor_sync(~0u, rm0, 1));
        rm0 = fmaxf(rm0, __shfl_xor_sync(~0u, rm0, 2));
        rm1 = fmaxf(rm1, __shfl_xor_sync(~0u, rm1, 1));
        rm1 = fmaxf(rm1, __shfl_xor_sync(~0u, rm1, 2));
        float corr0 = __expf(m0 - rm0), corr1 = __expf(m1 - rm1);
        m0 = rm0; m1 = rm1;

        float sum0 = 0.f, sum1 = 0.f;
        #pragma unroll
        for (int jn = 0; jn < 8; jn++) {
            float p0 = __expf(sc[jn][0] - m0), p1 = __expf(sc[jn][1] - m0);
            float p2 = __expf(sc[jn][2] - m1), p3 = __expf(sc[jn][3] - m1);
            sum0 += p0 + p1; sum1 += p2 + p3;
            __half2 hp0 = __floats2half2_rn(p0, p1);
            __half2 hp1 = __floats2half2_rn(p2, p3);
            Ph[r0 * APH + jn * 4 + t] = *(const uint32_t*)&hp0;
            Ph[(r0 + 8) * APH + jn * 4 + t] = *(const uint32_t*)&hp1;
        }
        sum0 += __shfl_xor_sync(~0u, sum0, 1);
        sum0 += __shfl_xor_sync(~0u, sum0, 2);
        sum1 += __shfl_xor_sync(~0u, sum1, 1);
        sum1 += __shfl_xor_sync(~0u, sum1, 2);
        l0 = fmaf(l0, corr0, sum0);
        l1 = fmaf(l1, corr1, sum1);
        #pragma unroll
        for (int jd = 0; jd < 8; jd++) {
            o[jd][0] *= corr0; o[jd][1] *= corr0;
            o[jd][2] *= corr1; o[jd][3] *= corr1;
        }
        __syncwarp();

        #pragma unroll
        for (int ks = 0; ks < 4; ks++) {
            uint32_t pa0 = Ph[r0 * APH + ks * 8 + t];
            uint32_t pa1 = Ph[(r0 + 8) * APH + ks * 8 + t];
            uint32_t pa2 = Ph[r0 * APH + ks * 8 + t + 4];
            uint32_t pa3 = Ph[(r0 + 8) * APH + ks * 8 + t + 4];
            #pragma unroll
            for (int jd = 0; jd < 8; jd++) {
                uint32_t vb0 = Vt[(jd * 8 + g) * APH + ks * 8 + t];
                uint32_t vb1 = Vt[(jd * 8 + g) * APH + ks * 8 + t + 4];
                mma_f16(o[jd], pa0, pa1, pa2, pa3, vb0, vb1);
            }
        }
    }

    float inv0 = 1.f / l0, inv1 = 1.f / l1;
    size_t row0g = ((size_t)(b * Sc + qb + r0)) * Dc + headoff;
    size_t row1g = row0g + (size_t)8 * Dc;
    #pragma unroll
    for (int jd = 0; jd < 8; jd++) {
        int col = jd * 8 + 2 * t;
        *(__half2*)&O[row0g + col] =
            __floats2half2_rn(o[jd][0] * inv0, o[jd][1] * inv0);
        *(__half2*)&O[row1g + col] =
            __floats2half2_rn(o[jd][2] * inv1, o[jd][3] * inv1);
    }
}

// ---------------- sparse attention for masked branches (fp16 in/out) ----------------
__global__ __launch_bounds__(128) void attn_sparse_k(const __half* __restrict__ Q,
                                                     const __half* __restrict__ Km,
                                                     const __half* __restrict__ Vm,
                                                     __half* __restrict__ O, int mode) {
    int w = threadIdx.x >> 5, lane = threadIdx.x & 31;
    int qi = blockIdx.x * 4 + w;
    int bh = blockIdx.y;
    int b = bh >> 4, h = bh & 15;
    size_t rowbase = ((size_t)(b * Sc + qi)) * Dc + (size_t)h * DHc;
    float q0 = __half2float(Q[rowbase + lane]);
    float q1 = __half2float(Q[rowbase + 32 + lane]);

    int k0i, nk;
    if (mode == 1) {
        k0i = qi - 1; nk = 3;
        if (qi == 0)      { k0i = 0; nk = 2; }
        if (qi == Sc - 1) { nk = 2; }
    } else {
        k0i = qi & ~1; nk = 2;
    }

    float s[3] = {0.f, 0.f, 0.f};
    #pragma unroll 3
    for (int kk = 0; kk < 3; kk++) {
        if (kk < nk) {
            size_t kb = ((size_t)(b * Sc + k0i + kk)) * Dc + (size_t)h * DHc;
            float acc = fmaf(q0, __half2float(Km[kb + lane]),
                             q1 * __half2float(Km[kb + 32 + lane]));
            #pragma unroll
            for (int off = 16; off; off >>= 1)
                acc += __shfl_xor_sync(~0u, acc, off);
            s[kk] = acc * 0.125f;
        }
    }
    float mx = s[0];
    for (int kk = 1; kk < nk; kk++) mx = fmaxf(mx, s[kk]);
    float p[3], l = 0.f;
    for (int kk = 0; kk < nk; kk++) { p[kk] = __expf(s[kk] - mx); l += p[kk]; }
    float inv = 1.f / l;

    float o0 = 0.f, o1 = 0.f;
    #pragma unroll 3
    for (int kk = 0; kk < 3; kk++) {
        if (kk < nk) {
            size_t vb = ((size_t)(b * Sc + k0i + kk)) * Dc + (size_t)h * DHc;
            o0 = fmaf(p[kk], __half2float(Vm[vb + lane]), o0);
            o1 = fmaf(p[kk], __half2float(Vm[vb + 32 + lane]), o1);
        }
    }
    O[rowbase + lane]      = __float2half_rn(o0 * inv);
    O[rowbase + 32 + lane] = __float2half_rn(o1 * inv);
}

// ---------------- fused gate + scale + concat ----------------
// Per token: logits_j = sum_d concat[d] * weff[d][j] + bg[j]; softmax;
// gsc[t][d] = g_{d>>10} * concat[d].
__global__ __launch_bounds__(256) void gatescale_k(const __half* __restrict__ Ao,
                                                   const float* __restrict__ weff,
                                                   const float* __restrict__ bg,
                                                   __half* __restrict__ gsc) {
    int t = blockIdx.x, tid = threadIdx.x;
    int d0 = tid * 16;
    int i = d0 >> 10, k = d0 & 1023;
    const __half* src = &Ao[(size_t)i * TOKD + (size_t)t * Dc + k];
    uint4 ra = *(const uint4*)src;
    uint4 rb = *(const uint4*)(src + 8);
    const __half* hv = (const __half*)&ra;
    const __half* hw = (const __half*)&rb;

    float4 acc = make_float4(0.f, 0.f, 0.f, 0.f);
    #pragma unroll
    for (int j = 0; j < 8; j++) {
        float v = __half2float(hv[j]);
        float4 wv = *(const float4*)&weff[(size_t)(d0 + j) * 4];
        acc.x = fmaf(v, wv.x, acc.x); acc.y = fmaf(v, wv.y, acc.y);
        acc.z = fmaf(v, wv.z, acc.z); acc.w = fmaf(v, wv.w, acc.w);
    }
    #pragma unroll
    for (int j = 0; j < 8; j++) {
        float v = __half2float(hw[j]);
        float4 wv = *(const float4*)&weff[(size_t)(d0 + 8 + j) * 4];
        acc.x = fmaf(v, wv.x, acc.x); acc.y = fmaf(v, wv.y, acc.y);
        acc.z = fmaf(v, wv.z, acc.z); acc.w = fmaf(v, wv.w, acc.w);
    }
    #pragma unroll
    for (int off = 16; off; off >>= 1) {
        acc.x += __shfl_xor_sync(~0u, acc.x, off);
        acc.y += __shfl_xor_sync(~0u, acc.y, off);
        acc.z += __shfl_xor_sync(~0u, acc.z, off);
        acc.w += __shfl_xor_sync(~0u, acc.w, off);
    }
    __shared__ float4 red[8];
    __shared__ float sg[4];
    if ((tid & 31) == 0) red[tid >> 5] = acc;
    __syncthreads();
    if (tid == 0) {
        float4 a = red[0];
        #pragma unroll
        for (int q = 1; q < 8; q++) {
            a.x += red[q].x; a.y += red[q].y; a.z += red[q].z; a.w += red[q].w;
        }
        float l0 = a.x + bg[0], l1 = a.y + bg[1], l2 = a.z + bg[2], l3 = a.w + bg[3];
        float mx = fmaxf(fmaxf(l0, l1), fmaxf(l2, l3));
        float e0 = __expf(l0 - mx), e1 = __expf(l1 - mx),
              e2 = __expf(l2 - mx), e3 = __expf(l3 - mx);
        float inv = 1.f / (e0 + e1 + e2 + e3);
        sg[0] = e0 * inv; sg[1] = e1 * inv; sg[2] = e2 * inv; sg[3] = e3 * inv;
    }
    __syncthreads();
    float gi = sg[i];
    __half ov[16];
    #pragma unroll
    for (int j = 0; j < 8; j++)
        ov[j] = __float2half_rn(gi * __half2float(hv[j]));
    #pragma unroll
    for (int j = 0; j < 8; j++)
        ov[8 + j] = __float2half_rn(gi * __half2float(hw[j]));
    __half* dst = &gsc[(size_t)t * 4096 + d0];
    *(uint4*)dst       = *(const uint4*)&ov[0];
    *(uint4*)(dst + 8) = *(const uint4*)&ov[8];
}

// ---------------- host launch ----------------
extern "C" void kernel_launch(void* const* d_in, const int* in_sizes, int n_in,
                              void* d_out, int out_size) {
    const float* x      = (const float*)d_in[0];
    const float* t_emb  = (const float*)d_in[1];
    const float* ln1_g  = (const float*)d_in[2];
    const float* ln1_b  = (const float*)d_in[3];
    const float* ln2_g  = (const float*)d_in[4];
    const float* ln2_b  = (const float*)d_in[5];
    const float* ada_w  = (const float*)d_in[6];
    const float* ada_b  = (const float*)d_in[7];

    const float *fus_wg, *fus_bg, *fus_wo, *ffn_w1, *ffn_w2, *ffn_w3;
    int ab;
    if (in_sizes[8] == 16384) {
        fus_wg = (const float*)d_in[8];  fus_bg = (const float*)d_in[9];
        fus_wo = (const float*)d_in[10];
        ffn_w1 = (const float*)d_in[11]; ffn_w2 = (const float*)d_in[12];
        ffn_w3 = (const float*)d_in[13];
        ab = 14;
    } else {
        ab = 8;
        fus_wg = (const float*)d_in[24]; fus_bg = (const float*)d_in[25];
        fus_wo = (const float*)d_in[26];
        ffn_w1 = (const float*)d_in[27]; ffn_w2 = (const float*)d_in[28];
        ffn_w3 = (const float*)d_in[29];
    }

    float  *st, *ada, *xmid, *weff;
    __half *wh, *wos, *wud, *nxh, *qkvh, *ao4h, *gsc, *fusedh, *h1h;
    cudaGetSymbolAddress((void**)&st,     g_st);
    cudaGetSymbolAddress((void**)&ada,    g_ada);
    cudaGetSymbolAddress((void**)&wh,     g_wh);
    cudaGetSymbolAddress((void**)&wos,    g_wos);
    cudaGetSymbolAddress((void**)&wud,    g_wud);
    cudaGetSymbolAddress((void**)&weff,   g_weff);
    cudaGetSymbolAddress((void**)&nxh,    g_nxh);
    cudaGetSymbolAddress((void**)&qkvh,   g_qkvh);
    cudaGetSymbolAddress((void**)&ao4h,   g_ao4h);
    cudaGetSymbolAddress((void**)&gsc,    g_gsc);
    cudaGetSymbolAddress((void**)&fusedh, g_fusedh);
    cudaGetSymbolAddress((void**)&xmid,   g_xmid);
    cudaGetSymbolAddress((void**)&h1h,    g_h1h);

    cudaFuncSetAttribute(attn_tc_k, cudaFuncAttributeMaxDynamicSharedMemorySize,
                         ATT_SMEM_BYTES);
    cudaFuncSetAttribute(gemm_tc, cudaFuncAttributeMaxDynamicSharedMemorySize,
                         GEMM_SMEM);

    float* out = (float*)d_out;

    // 0. weight prep
    TP17 tp;
    WoP wop;
    for (int p = 0; p < 4; p++) {
        tp.p[p * 3 + 0] = (const float*)d_in[ab + p * 4 + 0];
        tp.p[p * 3 + 1] = (const float*)d_in[ab + p * 4 + 1];
        tp.p[p * 3 + 2] = (const float*)d_in[ab + p * 4 + 2];
        tp.p[12 + p]    = (const float*)d_in[ab + p * 4 + 3];
        wop.p[p]        = (const float*)d_in[ab + p * 4 + 3];
    }
    tp.p[16] = fus_wo;
    wtrans17_k<<<dim3(32, 32, 17), 256>>>(tp, wh);
    wtrans_k<<<dim3(128, 32), 256>>>(ffn_w1, wh + W1, Dc, Fc);
    wtrans_k<<<dim3(128, 32), 256>>>(ffn_w3, wh + W3, Dc, Fc);
    wtrans_k<<<dim3(32, 128), 256>>>(ffn_w2, wh + W2, Fc, Dc);
    wostk_k<<<(4 << 20) / 2048, 256>>>(wh + WO, wos);
    wudstk_k<<<(8 << 20) / 2048, 256>>>(wh, wud);
    wgeff_k<<<512, 256>>>(wop, fus_wg, weff);

    // 1. AdaLN parameters
    silu_k<<<(Bc * Dc + 255) / 256, 256>>>(t_emb, st, Bc * Dc);
    ada_k<<<(Bc * SIXD) / 8, 256>>>(st, ada_w, ada_b, ada);

    // 2. nx = modulated LN(x), fp16
    ln_mod_k<<<TOK, 256>>>(x, ln1_g, ln1_b, ada, 0, Dc, nxh);

    // 3. all 12 QKV projections, fp16 output
    dim3 gQKV(Dc / 128, TOK / 128, 12);
    gemm_tc<<<gQKV, 256, GEMM_SMEM>>>(nxh, 0, wh + WQKV, (size_t)1 << 20,
                                      nullptr, qkvh, TOKD, TOK, Dc, Dc,
                                      nullptr, nullptr, 0);

    // 4. four attention branches (fp16 in/out)
    dim3 gAttn(Sc / 128, Bc * Hc);
    dim3 gSparse(Sc / 4, Bc * Hc);
    for (int p = 0; p < 4; p++) {
        const __half* q = qkvh + (size_t)(3 * p + 0) * TOKD;
        const __half* k = qkvh + (size_t)(3 * p + 1) * TOKD;
        const __half* v = qkvh + (size_t)(3 * p + 2) * TOKD;
        __half* ao = ao4h + (size_t)p * TOKD;
        if (p == 1 || p == 2)
            attn_sparse_k<<<gSparse, 128>>>(q, k, v, ao, p);
        else
            attn_tc_k<<<gAttn, 256, ATT_SMEM_BYTES>>>(q, k, v, ao, p);
    }

    // 5. fused gate+scale+concat, then one K=4096 GEMM through stacked Wo
    gatescale_k<<<TOK, 256>>>(ao4h, weff, fus_bg, gsc);
    dim3 gFuse(Dc / 128, TOK / 128, 1);
    gemm_tc<<<gFuse, 256, GEMM_SMEM>>>(gsc, 0, wos, 0,
                                       nullptr, fusedh, 0, TOK, Dc, 4 * Dc,
                                       nullptr, nullptr, 0);

    // 6. fus_wo projection + first residual (g_m at 2D)
    dim3 gProj(Dc / 128, TOK / 128, 1);
    gemm_tc<<<gProj, 256, GEMM_SMEM>>>(fusedh, 0, wh + WFUS, 0, xmid, nullptr, 0,
                                       TOK, Dc, Dc, x, ada + 2 * Dc, 0);

    // 7. FFN: up-proj with fused SwiGLU epilogue (interleaved w1/w3), then down
    ln_mod_k<<<TOK, 256>>>(xmid, ln2_g, ln2_b, ada, 3 * Dc, 4 * Dc, nxh);
    dim3 gUp(8192 / 128, TOK / 128, 1);
    gemm_tc<<<gUp, 256, GEMM_SMEM>>>(nxh, 0, wud, 0,
                                     nullptr, h1h, 0, TOK, 8192, Dc,
                                     nullptr, nullptr, 1);
    gemm_tc<<<gProj, 256, GEMM_SMEM>>>(h1h, 0, wh + W2, 0, out, nullptr, 0,
                                       TOK, Dc, Fc, xmid, ada + 5 * Dc, 0);
}

// round 13
// speedup vs baseline: 1.0438x; 1.0273x over previous
#include <cuda_runtime.h>
#include <cuda_fp16.h>
#include <math.h>
#include <stdint.h>

// Problem constants
#define Bc   4
#define Sc   1024
#define Dc   1024
#define Hc   16
#define DHc  64
#define Fc   4096
#define TOK  4096          // B*S
#define SIXD 6144          // 6*D
#define TOKD ((size_t)TOK * Dc)   // 4M
#define TOKF ((size_t)TOK * Fc)   // 16M

// ---------------- scratch (no allocations allowed) ----------------
__device__ float  g_st[Bc * Dc];
__device__ float  g_ada[Bc * SIXD];
__device__ __half g_wh[(size_t)29 << 20];    // transposed fp16 weights [N][K]
__device__ __half g_wos[4 << 20];            // stacked WoT [1024][4096]
__device__ __half g_wud[8 << 20];            // interleaved FFN-up wt [8192][1024]
__device__ float  g_weff[4 * Dc * 4];        // WgEff[i][k][j]
__device__ __half g_nxh[TOK * Dc];           // fp16 modulated LN output
__device__ __half g_qkvh[12 * TOK * Dc];     // q,k,v fp16
__device__ __half g_ao4h[4 * TOK * Dc];      // attention outputs fp16
__device__ __half g_gsc[TOK * 4 * Dc];       // gate-scaled concat [TOK][4096]
__device__ __half g_fusedh[TOK * Dc];        // fp16
__device__ float  g_xmid[TOK * Dc];
__device__ __half g_h1h[TOK * Fc];           // fp16 swiglu output (fused epilogue)

// weight scratch offsets (elements)
#define WQKV 0
#define WO   ((size_t)12 << 20)
#define WFUS ((size_t)16 << 20)
#define W1   ((size_t)17 << 20)
#define W3   ((size_t)21 << 20)
#define W2   ((size_t)25 << 20)

// ---------------- ptx helpers ----------------
__device__ __forceinline__ void mma_f16(float* c, uint32_t a0, uint32_t a1,
                                        uint32_t a2, uint32_t a3,
                                        uint32_t b0, uint32_t b1) {
    asm("mma.sync.aligned.m16n8k16.row.col.f32.f16.f16.f32 "
        "{%0,%1,%2,%3},{%4,%5,%6,%7},{%8,%9},{%0,%1,%2,%3};"
        : "+f"(c[0]), "+f"(c[1]), "+f"(c[2]), "+f"(c[3])
        : "r"(a0), "r"(a1), "r"(a2), "r"(a3), "r"(b0), "r"(b1));
}
__device__ __forceinline__ void ldsm_x4(uint32_t& r0, uint32_t& r1,
                                        uint32_t& r2, uint32_t& r3, uint32_t addr) {
    asm volatile("ldmatrix.sync.aligned.m8n8.x4.shared.b16 {%0,%1,%2,%3}, [%4];"
                 : "=r"(r0), "=r"(r1), "=r"(r2), "=r"(r3) : "r"(addr));
}
__device__ __forceinline__ void ldsm_x4_t(uint32_t& r0, uint32_t& r1,
                                          uint32_t& r2, uint32_t& r3, uint32_t addr) {
    asm volatile("ldmatrix.sync.aligned.m8n8.x4.trans.shared.b16 {%0,%1,%2,%3}, [%4];"
                 : "=r"(r0), "=r"(r1), "=r"(r2), "=r"(r3) : "r"(addr));
}
__device__ __forceinline__ void cp16s(uint32_t smem, const void* g) {
    asm volatile("cp.async.cg.shared.global [%0], [%1], 16;" :: "r"(smem), "l"(g));
}
__device__ __forceinline__ void cp_commit() {
    asm volatile("cp.async.commit_group;");
}
template <int N>
__device__ __forceinline__ void cp_wait() {
    asm volatile("cp.async.wait_group %0;" :: "n"(N));
}

// ---------------- weight prep ----------------
__global__ __launch_bounds__(256) void wtrans_k(const float* __restrict__ in,
                                                __half* __restrict__ out,
                                                int Kd, int Nd) {
    __shared__ float tile[32][33];
    int n0 = blockIdx.x * 32, k0 = blockIdx.y * 32;
    int tx = threadIdx.x & 31, ty = threadIdx.x >> 5;
    #pragma unroll
    for (int i = 0; i < 32; i += 8)
        tile[ty + i][tx] = in[(size_t)(k0 + ty + i) * Nd + n0 + tx];
    __syncthreads();
    #pragma unroll
    for (int i = 0; i < 32; i += 8)
        out[(size_t)(n0 + ty + i) * Kd + k0 + tx] = __float2half_rn(tile[tx][ty + i]);
}

struct TP17 { const float* p[17]; };
__global__ __launch_bounds__(256) void wtrans17_k(TP17 tp, __half* __restrict__ out) {
    __shared__ float tile[32][33];
    const float* in = tp.p[blockIdx.z];
    __half* o = out + ((size_t)blockIdx.z << 20);
    int n0 = blockIdx.x * 32, k0 = blockIdx.y * 32;
    int tx = threadIdx.x & 31, ty = threadIdx.x >> 5;
    #pragma unroll
    for (int i = 0; i < 32; i += 8)
        tile[ty + i][tx] = in[(size_t)(k0 + ty + i) * Dc + n0 + tx];
    __syncthreads();
    #pragma unroll
    for (int i = 0; i < 32; i += 8)
        o[(size_t)(n0 + ty + i) * Dc + k0 + tx] = __float2half_rn(tile[tx][ty + i]);
}

// stacked WoT: out[n][i*1024+k] = whWO[i][n][k]
__global__ __launch_bounds__(256) void wostk_k(const __half* __restrict__ whWO,
                                               __half* __restrict__ out) {
    int idx8 = (blockIdx.x * 256 + threadIdx.x) * 8;
    int n = idx8 >> 12;
    int r = idx8 & 4095;
    int i = r >> 10, k = r & 1023;
    uint4 v = *(const uint4*)&whWO[((size_t)i << 20) + n * 1024 + k];
    *(uint4*)&out[(size_t)n * 4096 + r] = v;
}

// interleaved FFN-up weight: row 2c = w1T[c], row 2c+1 = w3T[c]
__global__ __launch_bounds__(256) void wudstk_k(const __half* __restrict__ wh,
                                                __half* __restrict__ out) {
    size_t idx8 = ((size_t)blockIdx.x * 256 + threadIdx.x) * 8;   // 8M halves
    int n = (int)(idx8 >> 10);
    int k = (int)(idx8 & 1023);
    int c = n >> 1, o = n & 1;
    const __half* src = wh + (o ? W3 : W1) + (size_t)c * 1024 + k;
    *(uint4*)&out[(size_t)n * 1024 + k] = *(const uint4*)src;
}

// WgEff[i][k][j] = sum_n Wo_i[k][n] * wg[(i*1024+n)*4+j]
struct WoP { const float* p[4]; };
__global__ __launch_bounds__(256) void wgeff_k(WoP wo, const float* __restrict__ wg,
                                               float* __restrict__ weff) {
    int o = blockIdx.x * 8 + (threadIdx.x >> 5);
    int lane = threadIdx.x & 31;
    int i = o >> 10, k = o & 1023;
    const float* wrow = wo.p[i] + (size_t)k * Dc;
    float4 acc = make_float4(0.f, 0.f, 0.f, 0.f);
    for (int n = lane; n < Dc; n += 32) {
        float wv = wrow[n];
        float4 gv = *(const float4*)&wg[(size_t)(i * Dc + n) * 4];
        acc.x = fmaf(wv, gv.x, acc.x);
        acc.y = fmaf(wv, gv.y, acc.y);
        acc.z = fmaf(wv, gv.z, acc.z);
        acc.w = fmaf(wv, gv.w, acc.w);
    }
    #pragma unroll
    for (int off = 16; off; off >>= 1) {
        acc.x += __shfl_xor_sync(~0u, acc.x, off);
        acc.y += __shfl_xor_sync(~0u, acc.y, off);
        acc.z += __shfl_xor_sync(~0u, acc.z, off);
        acc.w += __shfl_xor_sync(~0u, acc.w, off);
    }
    if (!lane) *(float4*)&weff[(size_t)o * 4] = acc;
}

// ---------------- elementwise helpers ----------------
__global__ void silu_k(const float* __restrict__ in, float* __restrict__ out, int n) {
    int i = blockIdx.x * blockDim.x + threadIdx.x;
    if (i < n) { float v = in[i]; out[i] = v / (1.f + __expf(-v)); }
}

__global__ __launch_bounds__(256) void ada_k(const float* __restrict__ st,
                                             const float* __restrict__ W,
                                             const float* __restrict__ bias,
                                             float* __restrict__ out) {
    int o = blockIdx.x * 8 + (threadIdx.x >> 5);
    int lane = threadIdx.x & 31;
    int b = o / SIXD, n = o - b * SIXD;
    float acc = 0.f;
    for (int k = lane; k < Dc; k += 32)
        acc = fmaf(st[b * Dc + k], W[(size_t)k * SIXD + n], acc);
    #pragma unroll
    for (int off = 16; off; off >>= 1) acc += __shfl_xor_sync(~0u, acc, off);
    if (!lane) out[o] = acc + bias[n];
}

__global__ __launch_bounds__(256) void ln_mod_k(const float* __restrict__ X,
                                                const float* __restrict__ gam,
                                                const float* __restrict__ bet,
                                                const float* __restrict__ ada,
                                                int sh_off, int sc_off,
                                                __half* __restrict__ out) {
    int t = blockIdx.x;
    int b = t >> 10;
    int tid = threadIdx.x;
    const float* xr = X + (size_t)t * Dc;
    float s = 0.f, ss = 0.f;
    for (int i = tid; i < Dc; i += 256) { float v = xr[i]; s += v; ss = fmaf(v, v, ss); }
    __shared__ float r1[8], r2[8];
    __shared__ float muS, rsS;
    #pragma unroll
    for (int off = 16; off; off >>= 1) {
        s  += __shfl_xor_sync(~0u, s,  off);
        ss += __shfl_xor_sync(~0u, ss, off);
    }
    if ((tid & 31) == 0) { r1[tid >> 5] = s; r2[tid >> 5] = ss; }
    __syncthreads();
    if (tid < 32) {
        float a = (tid < 8) ? r1[tid] : 0.f;
        float c = (tid < 8) ? r2[tid] : 0.f;
        #pragma unroll
        for (int off = 4; off; off >>= 1) {
            a += __shfl_xor_sync(~0u, a, off);
            c += __shfl_xor_sync(~0u, c, off);
        }
        if (tid == 0) {
            float mu = a * (1.f / Dc);
            float var = c * (1.f / Dc) - mu * mu;
            muS = mu; rsS = rsqrtf(var + 1e-6f);
        }
    }
    __syncthreads();
    float mu = muS, rs = rsS;
    const float* ar = ada + b * SIXD;
    __half* orow = out + (size_t)t * Dc;
    for (int i = tid; i < Dc; i += 256) {
        float v = (xr[i] - mu) * rs * gam[i] + bet[i];
        orow[i] = __float2half_rn(fmaf(v, 1.f + ar[sc_off + i], ar[sh_off + i]));
    }
}

// ---------------- FP16 TC GEMM: 128x128 tile, ldmatrix + m16n8k16 ----------------
#define RS   40
#define ASZh (128 * RS)
#define STGh (2 * ASZh)
#define NSTG 4
#define STGB (STGh * 2)
#define GEMM_SMEM (NSTG * STGB)      // 81920 B

__global__ __launch_bounds__(256, 2) void gemm_tc(
    const __half* __restrict__ A, size_t azs,
    const __half* __restrict__ Bt, size_t bzs,
    float* __restrict__ C, __half* __restrict__ Ch, size_t czs,
    int M, int N, int K,
    const float* __restrict__ resid, const float* __restrict__ gate,
    int swiglu) {
    extern __shared__ char smraw[];
    uint32_t smbase = (uint32_t)__cvta_generic_to_shared(smraw);

    A += azs * blockIdx.z; Bt += bzs * blockIdx.z;
    if (Ch) Ch += czs * blockIdx.z; else C += czs * blockIdx.z;

    int tid = threadIdx.x;
    int bx = blockIdx.x, by = blockIdx.y;
    int w = tid >> 5, lane = tid & 31;
    int wm = (w >> 2) * 64, wn = (w & 3) * 32;
    int g = lane >> 2, t = lane & 3;
    int lm = lane & 7, lq = lane >> 3;

    float acc[4][4][4];
    #pragma unroll
    for (int i = 0; i < 4; i++)
        #pragma unroll
        for (int j = 0; j < 4; j++)
            #pragma unroll
            for (int r = 0; r < 4; r++) acc[i][j][r] = 0.f;

    const __half* Ag = A + (size_t)(by * 128) * K;
    const __half* Bg = Bt + (size_t)(bx * 128) * K;

    uint32_t aoff[4], boff[2];
    {
        int koff = (lq >> 1) * 8;
        int rA = lm + 8 * (lq & 1);
        #pragma unroll
        for (int i = 0; i < 4; i++)
            aoff[i] = (uint32_t)(((wm + 16 * i + rA) * RS + koff) * 2);
        #pragma unroll
        for (int jp = 0; jp < 2; jp++)
            boff[jp] = (uint32_t)((ASZh + (wn + 16 * jp + 8 * (lq & 1) + lm) * RS + koff) * 2);
    }

    int r0 = tid >> 2;
    int p8 = (tid & 3) * 8;

    auto load_stage = [&](int st, int k0) {
        uint32_t As = smbase + st * STGB;
        uint32_t Bs = As + ASZh * 2;
        cp16s(As + (r0 * RS + p8) * 2,        Ag + (size_t)r0 * K + k0 + p8);
        cp16s(As + ((r0 + 64) * RS + p8) * 2, Ag + (size_t)(r0 + 64) * K + k0 + p8);
        cp16s(Bs + (r0 * RS + p8) * 2,        Bg + (size_t)r0 * K + k0 + p8);
        cp16s(Bs + ((r0 + 64) * RS + p8) * 2, Bg + (size_t)(r0 + 64) * K + k0 + p8);
    };

    load_stage(0, 0);  cp_commit();
    load_stage(1, 32); cp_commit();
    load_stage(2, 64); cp_commit();
    int cur = 0;
    int nch = K >> 5;

    for (int c = 0; c < nch; c++) {
        cp_wait<2>();
        __syncthreads();
        if (c + 3 < nch) {
            int nst = cur + 3; if (nst >= NSTG) nst -= NSTG;
            load_stage(nst, (c + 3) * 32);
        }
        cp_commit();

        uint32_t stb = smbase + cur * STGB;
        #pragma unroll
        for (int ks = 0; ks < 2; ks++) {
            uint32_t kadd = stb + ks * 32;
            uint32_t af[4][4], bf[4][2];
            #pragma unroll
            for (int i = 0; i < 4; i++)
                ldsm_x4(af[i][0], af[i][1], af[i][2], af[i][3], kadd + aoff[i]);
            #pragma unroll
            for (int jp = 0; jp < 2; jp++)
                ldsm_x4(bf[2 * jp][0], bf[2 * jp + 1][0],
                        bf[2 * jp][1], bf[2 * jp + 1][1], kadd + boff[jp]);
            #pragma unroll
            for (int i = 0; i < 4; i++)
                #pragma unroll
                for (int j = 0; j < 4; j++)
                    mma_f16(acc[i][j], af[i][0], af[i][1], af[i][2], af[i][3],
                            bf[j][0], bf[j][1]);
        }
        cur++; if (cur >= NSTG) cur -= NSTG;
    }

    #pragma unroll
    for (int i = 0; i < 4; i++) {
        #pragma unroll
        for (int j = 0; j < 4; j++) {
            int row0 = by * 128 + wm + 16 * i + g;
            int col  = bx * 128 + wn + 8 * j + 2 * t;
            if (swiglu) {
                int halfN = N >> 1;
                int outc = col >> 1;
                float a0 = acc[i][j][0], b0v = acc[i][j][1];
                float a1 = acc[i][j][2], b1v = acc[i][j][3];
                float s0 = (a0 / (1.f + __expf(-a0))) * b0v;
                float s1 = (a1 / (1.f + __expf(-a1))) * b1v;
                Ch[(size_t)row0 * halfN + outc]       = __float2half_rn(s0);
                Ch[(size_t)(row0 + 8) * halfN + outc] = __float2half_rn(s1);
                continue;
            }
            size_t b0i = (size_t)row0 * N + col;
            size_t b1i = (size_t)(row0 + 8) * N + col;
            if (Ch) {
                *(__half2*)&Ch[b0i] = __floats2half2_rn(acc[i][j][0], acc[i][j][1]);
                *(__half2*)&Ch[b1i] = __floats2half2_rn(acc[i][j][2], acc[i][j][3]);
            } else if (resid == nullptr) {
                *(float2*)&C[b0i] = make_float2(acc[i][j][0], acc[i][j][1]);
                *(float2*)&C[b1i] = make_float2(acc[i][j][2], acc[i][j][3]);
            } else {
                int bb0 = row0 >> 10, bb1 = (row0 + 8) >> 10;
                float2 gr0 = *(const float2*)&gate[(size_t)bb0 * SIXD + col];
                float2 gr1 = *(const float2*)&gate[(size_t)bb1 * SIXD + col];
                float2 rv0 = *(const float2*)&resid[b0i];
                float2 rv1 = *(const float2*)&resid[b1i];
                *(float2*)&C[b0i] = make_float2(fmaf(gr0.x, acc[i][j][0], rv0.x),
                                                fmaf(gr0.y, acc[i][j][1], rv0.y));
                *(float2*)&C[b1i] = make_float2(fmaf(gr1.x, acc[i][j][2], rv1.x),
                                                fmaf(gr1.y, acc[i][j][3], rv1.y));
            }
        }
    }
}

// ---------------- fp16 flash attention: ldmatrix + cp.async double buffer ----------
// smem words: Ph[128][36] | {K,V}[2 stages][64][36] each
#define APH 36
#define ATT_TSTG (64 * APH)                       // 2304 words per K or V tile
#define ATT_SMEM_BYTES ((128 * APH + 4 * ATT_TSTG) * 4)   // 55296 B

__global__ __launch_bounds__(256) void attn_tc_k(const __half* __restrict__ Q,
                                                 const __half* __restrict__ Km,
                                                 const __half* __restrict__ Vm,
                                                 __half* __restrict__ O, int branch) {
    extern __shared__ uint32_t smu[];
    uint32_t* Ph = smu;
    uint32_t smb = (uint32_t)__cvta_generic_to_shared(smu);
    int tid = threadIdx.x, lane = tid & 31, w = tid >> 5;
    int g = lane >> 2, t = lane & 3;
    int lm = lane & 7, lq = lane >> 3;
    int bh = blockIdx.y;
    int b = bh >> 4, h = bh & 15;
    int qb = blockIdx.x * 128;
    int headoff = h * DHc;

    // stage Q: 128 rows x 8 uint4
    #pragma unroll
    for (int i = 0; i < 4; i++) {
        int idx = tid + i * 256;
        int row = idx >> 3, q4 = idx & 7;
        uint4 v = *(const uint4*)&Q[((size_t)(b * Sc + qb + row)) * Dc + headoff + q4 * 8];
        *(uint4*)&Ph[row * APH + q4 * 4] = v;
    }
    __syncthreads();

    int r0 = w * 16 + g;
    uint32_t qa[4][4];
    #pragma unroll
    for (int kk = 0; kk < 4; kk++) {
        qa[kk][0] = Ph[r0 * APH + kk * 8 + t];
        qa[kk][1] = Ph[(r0 + 8) * APH + kk * 8 + t];
        qa[kk][2] = Ph[r0 * APH + kk * 8 + t + 4];
        qa[kk][3] = Ph[(r0 + 8) * APH + kk * 8 + t + 4];
    }
    __syncthreads();   // Q fragments consumed before Ph reused for P

    // ldmatrix per-lane offsets (bytes; row stride 144 B)
    uint32_t kboff = (uint32_t)((8 * (lq & 1) + lm) * 144 + (lq >> 1) * 16);   // + jp*16*144 + kk*32
    uint32_t vboff = (uint32_t)((8 * (lq >> 1) + lm) * 144 + (lq & 1) * 16);   // + ks*16*144 + jp*32
    uint32_t paoff = smb + (uint32_t)((w * 16 + 8 * (lq & 1) + lm) * 144 + (lq >> 1) * 16); // + ks*32

    float m0 = -INFINITY, m1 = -INFINITY, l0 = 0.f, l1 = 0.f;
    float o[8][4];
    #pragma unroll
    for (int j = 0; j < 8; j++)
        #pragma unroll
        for (int r = 0; r < 4; r++) o[j][r] = 0.f;

    int qi0 = qb + r0, qi1 = qi0 + 8;

    int cr = tid >> 3, cs = (tid & 7);   // cp rows/segs
    auto load_kv = [&](int st, int kt) {
        uint32_t kb = smb + (128 * APH + st * 2 * ATT_TSTG) * 4;
        uint32_t vb = kb + ATT_TSTG * 4;
        #pragma unroll
        for (int i = 0; i < 2; i++) {
            int row = cr + i * 32;
            size_t gsrc = ((size_t)(b * Sc + kt + row)) * Dc + headoff + cs * 8;
            uint32_t doff = (uint32_t)((row * APH + cs * 4) * 4);
            cp16s(kb + doff, Km + gsrc);
            cp16s(vb + doff, Vm + gsrc);
        }
    };

    load_kv(0, 0);
    cp_commit();

    for (int it = 0; it < 16; it++) {
        cp_wait<0>();
        __syncthreads();
        if (it + 1 < 16) { load_kv((it + 1) & 1, (it + 1) * 64); cp_commit(); }

        uint32_t kb = smb + (128 * APH + (it & 1) * 2 * ATT_TSTG) * 4;
        uint32_t vb = kb + ATT_TSTG * 4;
        int kt = it * 64;

        // scores: Q(16x64) @ K^T(64 keys) ; B via ldmatrix on K rows [key][d]
        float sc[8][4];
        #pragma unroll
        for (int jn = 0; jn < 8; jn++)
            #pragma unroll
            for (int r = 0; r < 4; r++) sc[jn][r] = 0.f;
        #pragma unroll
        for (int kk = 0; kk < 4; kk++) {
            uint32_t bf[8][2];
            #pragma unroll
            for (int jp = 0; jp < 4; jp++)
                ldsm_x4(bf[2 * jp][0], bf[2 * jp + 1][0],
                        bf[2 * jp][1], bf[2 * jp + 1][1],
                        kb + jp * (16 * 144) + kk * 32 + kboff);
            #pragma unroll
            for (int jn = 0; jn < 8; jn++)
                mma_f16(sc[jn], qa[kk][0], qa[kk][1], qa[kk][2], qa[kk][3],
                        bf[jn][0], bf[jn][1]);
        }

        float rm0 = m0, rm1 = m1;
        #pragma unroll
        for (int jn = 0; jn < 8; jn++) {
            int kj = kt + jn * 8 + 2 * t;
            float b00 = 0.f, b01 = 0.f, b10 = 0.f, b11 = 0.f;
            if (branch == 0) {
                b00 = -(float)abs(qi0 - kj);     b01 = -(float)abs(qi0 - kj - 1);
                b10 = -(float)abs(qi1 - kj);     b11 = -(float)abs(qi1 - kj - 1);
            }
            sc[jn][0] = fmaf(sc[jn][0], 0.125f, b00);
            sc[jn][1] = fmaf(sc[jn][1], 0.125f, b01);
            sc[jn][2] = fmaf(sc[jn][2], 0.125f, b10);
            sc[jn][3] = fmaf(sc[jn][3], 0.125f, b11);
            rm0 = fmaxf(rm0, fmaxf(sc[jn][0], sc[jn][1]));
            rm1 = fmaxf(rm1, fmaxf(sc[jn][2], sc[jn][3]));
        }
        rm0 = fmaxf(rm0, __shfl_xor_sync(~0u, rm0, 1));
        rm0 = fmaxf(rm0, __shfl_xor_sync(~0u, rm0, 2));
        rm1 = fmaxf(rm1, __shfl_xor_sync(~0u, rm1, 1));
        rm1 = fmaxf(rm1, __shfl_xor_sync(~0u, rm1, 2));
        float corr0 = __expf(m0 - rm0), corr1 = __expf(m1 - rm1);
        m0 = rm0; m1 = rm1;

        float sum0 = 0.f, sum1 = 0.f;
        #pragma unroll
        for (int jn = 0; jn < 8; jn++) {
            float p0 = __expf(sc[jn][0] - m0), p1 = __expf(sc[jn][1] - m0);
            float p2 = __expf(sc[jn][2] - m1), p3 = __expf(sc[jn][3] - m1);
            sum0 += p0 + p1; sum1 += p2 + p3;
            __half2 hp0 = __floats2half2_rn(p0, p1);
            __half2 hp1 = __floats2half2_rn(p2, p3);
            Ph[r0 * APH + jn * 4 + t] = *(const uint32_t*)&hp0;
            Ph[(r0 + 8) * APH + jn * 4 + t] = *(const uint32_t*)&hp1;
        }
        sum0 += __shfl_xor_sync(~0u, sum0, 1);
        sum0 += __shfl_xor_sync(~0u, sum0, 2);
        sum1 += __shfl_xor_sync(~0u, sum1, 1);
        sum1 += __shfl_xor_sync(~0u, sum1, 2);
        l0 = fmaf(l0, corr0, sum0);
        l1 = fmaf(l1, corr1, sum1);
        #pragma unroll
        for (int jd = 0; jd < 8; jd++) {
            o[jd][0] *= corr0; o[jd][1] *= corr0;
            o[jd][2] *= corr1; o[jd][3] *= corr1;
        }
        __syncwarp();   // P rows are warp-private

        // PV: A = P via ldmatrix (own rows), B = V via ldmatrix.trans on [key][d]
        #pragma unroll
        for (int ks = 0; ks < 4; ks++) {
            uint32_t pa[4];
            ldsm_x4(pa[0], pa[1], pa[2], pa[3], paoff + ks * 32);
            uint32_t bf[8][2];
            #pragma unroll
            for (int jp = 0; jp < 4; jp++)
                ldsm_x4_t(bf[2 * jp][0], bf[2 * jp + 1][0],
                          bf[2 * jp][1], bf[2 * jp + 1][1],
                          vb + ks * (16 * 144) + jp * 32 + vboff);
            #pragma unroll
            for (int jd = 0; jd < 8; jd++)
                mma_f16(o[jd], pa[0], pa[1], pa[2], pa[3], bf[jd][0], bf[jd][1]);
        }
    }

    float inv0 = 1.f / l0, inv1 = 1.f / l1;
    size_t row0g = ((size_t)(b * Sc + qb + r0)) * Dc + headoff;
    size_t row1g = row0g + (size_t)8 * Dc;
    #pragma unroll
    for (int jd = 0; jd < 8; jd++) {
        int col = jd * 8 + 2 * t;
        *(__half2*)&O[row0g + col] =
            __floats2half2_rn(o[jd][0] * inv0, o[jd][1] * inv0);
        *(__half2*)&O[row1g + col] =
            __floats2half2_rn(o[jd][2] * inv1, o[jd][3] * inv1);
    }
}

// ---------------- sparse attention for masked branches (fp16 in/out) ----------------
__global__ __launch_bounds__(128) void attn_sparse_k(const __half* __restrict__ Q,
                                                     const __half* __restrict__ Km,
                                                     const __half* __restrict__ Vm,
                                                     __half* __restrict__ O, int mode) {
    int w = threadIdx.x >> 5, lane = threadIdx.x & 31;
    int qi = blockIdx.x * 4 + w;
    int bh = blockIdx.y;
    int b = bh >> 4, h = bh & 15;
    size_t rowbase = ((size_t)(b * Sc + qi)) * Dc + (size_t)h * DHc;
    float q0 = __half2float(Q[rowbase + lane]);
    float q1 = __half2float(Q[rowbase + 32 + lane]);

    int k0i, nk;
    if (mode == 1) {
        k0i = qi - 1; nk = 3;
        if (qi == 0)      { k0i = 0; nk = 2; }
        if (qi == Sc - 1) { nk = 2; }
    } else {
        k0i = qi & ~1; nk = 2;
    }

    float s[3] = {0.f, 0.f, 0.f};
    #pragma unroll 3
    for (int kk = 0; kk < 3; kk++) {
        if (kk < nk) {
            size_t kb = ((size_t)(b * Sc + k0i + kk)) * Dc + (size_t)h * DHc;
            float acc = fmaf(q0, __half2float(Km[kb + lane]),
                             q1 * __half2float(Km[kb + 32 + lane]));
            #pragma unroll
            for (int off = 16; off; off >>= 1)
                acc += __shfl_xor_sync(~0u, acc, off);
            s[kk] = acc * 0.125f;
        }
    }
    float mx = s[0];
    for (int kk = 1; kk < nk; kk++) mx = fmaxf(mx, s[kk]);
    float p[3], l = 0.f;
    for (int kk = 0; kk < nk; kk++) { p[kk] = __expf(s[kk] - mx); l += p[kk]; }
    float inv = 1.f / l;

    float o0 = 0.f, o1 = 0.f;
    #pragma unroll 3
    for (int kk = 0; kk < 3; kk++) {
        if (kk < nk) {
            size_t vb = ((size_t)(b * Sc + k0i + kk)) * Dc + (size_t)h * DHc;
            o0 = fmaf(p[kk], __half2float(Vm[vb + lane]), o0);
            o1 = fmaf(p[kk], __half2float(Vm[vb + 32 + lane]), o1);
        }
    }
    O[rowbase + lane]      = __float2half_rn(o0 * inv);
    O[rowbase + 32 + lane] = __float2half_rn(o1 * inv);
}

// ---------------- fused gate + scale + concat ----------------
__global__ __launch_bounds__(256) void gatescale_k(const __half* __restrict__ Ao,
                                                   const float* __restrict__ weff,
                                                   const float* __restrict__ bg,
                                                   __half* __restrict__ gsc) {
    int t = blockIdx.x, tid = threadIdx.x;
    int d0 = tid * 16;
    int i = d0 >> 10, k = d0 & 1023;
    const __half* src = &Ao[(size_t)i * TOKD + (size_t)t * Dc + k];
    uint4 ra = *(const uint4*)src;
    uint4 rb = *(const uint4*)(src + 8);
    const __half* hv = (const __half*)&ra;
    const __half* hw = (const __half*)&rb;

    float4 acc = make_float4(0.f, 0.f, 0.f, 0.f);
    #pragma unroll
    for (int j = 0; j < 8; j++) {
        float v = __half2float(hv[j]);
        float4 wv = *(const float4*)&weff[(size_t)(d0 + j) * 4];
        acc.x = fmaf(v, wv.x, acc.x); acc.y = fmaf(v, wv.y, acc.y);
        acc.z = fmaf(v, wv.z, acc.z); acc.w = fmaf(v, wv.w, acc.w);
    }
    #pragma unroll
    for (int j = 0; j < 8; j++) {
        float v = __half2float(hw[j]);
        float4 wv = *(const float4*)&weff[(size_t)(d0 + 8 + j) * 4];
        acc.x = fmaf(v, wv.x, acc.x); acc.y = fmaf(v, wv.y, acc.y);
        acc.z = fmaf(v, wv.z, acc.z); acc.w = fmaf(v, wv.w, acc.w);
    }
    #pragma unroll
    for (int off = 16; off; off >>= 1) {
        acc.x += __shfl_xor_sync(~0u, acc.x, off);
        acc.y += __shfl_xor_sync(~0u, acc.y, off);
        acc.z += __shfl_xor_sync(~0u, acc.z, off);
        acc.w += __shfl_xor_sync(~0u, acc.w, off);
    }
    __shared__ float4 red[8];
    __shared__ float sg[4];
    if ((tid & 31) == 0) red[tid >> 5] = acc;
    __syncthreads();
    if (tid == 0) {
        float4 a = red[0];
        #pragma unroll
        for (int q = 1; q < 8; q++) {
            a.x += red[q].x; a.y += red[q].y; a.z += red[q].z; a.w += red[q].w;
        }
        float l0 = a.x + bg[0], l1 = a.y + bg[1], l2 = a.z + bg[2], l3 = a.w + bg[3];
        float mx = fmaxf(fmaxf(l0, l1), fmaxf(l2, l3));
        float e0 = __expf(l0 - mx), e1 = __expf(l1 - mx),
              e2 = __expf(l2 - mx), e3 = __expf(l3 - mx);
        float inv = 1.f / (e0 + e1 + e2 + e3);
        sg[0] = e0 * inv; sg[1] = e1 * inv; sg[2] = e2 * inv; sg[3] = e3 * inv;
    }
    __syncthreads();
    float gi = sg[i];
    __half ov[16];
    #pragma unroll
    for (int j = 0; j < 8; j++)
        ov[j] = __float2half_rn(gi * __half2float(hv[j]));
    #pragma unroll
    for (int j = 0; j < 8; j++)
        ov[8 + j] = __float2half_rn(gi * __half2float(hw[j]));
    __half* dst = &gsc[(size_t)t * 4096 + d0];
    *(uint4*)dst       = *(const uint4*)&ov[0];
    *(uint4*)(dst + 8) = *(const uint4*)&ov[8];
}

// ---------------- host launch ----------------
extern "C" void kernel_launch(void* const* d_in, const int* in_sizes, int n_in,
                              void* d_out, int out_size) {
    const float* x      = (const float*)d_in[0];
    const float* t_emb  = (const float*)d_in[1];
    const float* ln1_g  = (const float*)d_in[2];
    const float* ln1_b  = (const float*)d_in[3];
    const float* ln2_g  = (const float*)d_in[4];
    const float* ln2_b  = (const float*)d_in[5];
    const float* ada_w  = (const float*)d_in[6];
    const float* ada_b  = (const float*)d_in[7];

    const float *fus_wg, *fus_bg, *fus_wo, *ffn_w1, *ffn_w2, *ffn_w3;
    int ab;
    if (in_sizes[8] == 16384) {
        fus_wg = (const float*)d_in[8];  fus_bg = (const float*)d_in[9];
        fus_wo = (const float*)d_in[10];
        ffn_w1 = (const float*)d_in[11]; ffn_w2 = (const float*)d_in[12];
        ffn_w3 = (const float*)d_in[13];
        ab = 14;
    } else {
        ab = 8;
        fus_wg = (const float*)d_in[24]; fus_bg = (const float*)d_in[25];
        fus_wo = (const float*)d_in[26];
        ffn_w1 = (const float*)d_in[27]; ffn_w2 = (const float*)d_in[28];
        ffn_w3 = (const float*)d_in[29];
    }

    float  *st, *ada, *xmid, *weff;
    __half *wh, *wos, *wud, *nxh, *qkvh, *ao4h, *gsc, *fusedh, *h1h;
    cudaGetSymbolAddress((void**)&st,     g_st);
    cudaGetSymbolAddress((void**)&ada,    g_ada);
    cudaGetSymbolAddress((void**)&wh,     g_wh);
    cudaGetSymbolAddress((void**)&wos,    g_wos);
    cudaGetSymbolAddress((void**)&wud,    g_wud);
    cudaGetSymbolAddress((void**)&weff,   g_weff);
    cudaGetSymbolAddress((void**)&nxh,    g_nxh);
    cudaGetSymbolAddress((void**)&qkvh,   g_qkvh);
    cudaGetSymbolAddress((void**)&ao4h,   g_ao4h);
    cudaGetSymbolAddress((void**)&gsc,    g_gsc);
    cudaGetSymbolAddress((void**)&fusedh, g_fusedh);
    cudaGetSymbolAddress((void**)&xmid,   g_xmid);
    cudaGetSymbolAddress((void**)&h1h,    g_h1h);

    cudaFuncSetAttribute(attn_tc_k, cudaFuncAttributeMaxDynamicSharedMemorySize,
                         ATT_SMEM_BYTES);
    cudaFuncSetAttribute(gemm_tc, cudaFuncAttributeMaxDynamicSharedMemorySize,
                         GEMM_SMEM);

    float* out = (float*)d_out;

    // 0. weight prep
    TP17 tp;
    WoP wop;
    for (int p = 0; p < 4; p++) {
        tp.p[p * 3 + 0] = (const float*)d_in[ab + p * 4 + 0];
        tp.p[p * 3 + 1] = (const float*)d_in[ab + p * 4 + 1];
        tp.p[p * 3 + 2] = (const float*)d_in[ab + p * 4 + 2];
        tp.p[12 + p]    = (const float*)d_in[ab + p * 4 + 3];
        wop.p[p]        = (const float*)d_in[ab + p * 4 + 3];
    }
    tp.p[16] = fus_wo;
    wtrans17_k<<<dim3(32, 32, 17), 256>>>(tp, wh);
    wtrans_k<<<dim3(128, 32), 256>>>(ffn_w1, wh + W1, Dc, Fc);
    wtrans_k<<<dim3(128, 32), 256>>>(ffn_w3, wh + W3, Dc, Fc);
    wtrans_k<<<dim3(32, 128), 256>>>(ffn_w2, wh + W2, Fc, Dc);
    wostk_k<<<(4 << 20) / 2048, 256>>>(wh + WO, wos);
    wudstk_k<<<(8 << 20) / 2048, 256>>>(wh, wud);
    wgeff_k<<<512, 256>>>(wop, fus_wg, weff);

    // 1. AdaLN parameters
    silu_k<<<(Bc * Dc + 255) / 256, 256>>>(t_emb, st, Bc * Dc);
    ada_k<<<(Bc * SIXD) / 8, 256>>>(st, ada_w, ada_b, ada);

    // 2. nx = modulated LN(x), fp16
    ln_mod_k<<<TOK, 256>>>(x, ln1_g, ln1_b, ada, 0, Dc, nxh);

    // 3. all 12 QKV projections, fp16 output
    dim3 gQKV(Dc / 128, TOK / 128, 12);
    gemm_tc<<<gQKV, 256, GEMM_SMEM>>>(nxh, 0, wh + WQKV, (size_t)1 << 20,
                                      nullptr, qkvh, TOKD, TOK, Dc, Dc,
                                      nullptr, nullptr, 0);

    // 4. four attention branches (fp16 in/out)
    dim3 gAttn(Sc / 128, Bc * Hc);
    dim3 gSparse(Sc / 4, Bc * Hc);
    for (int p = 0; p < 4; p++) {
        const __half* q = qkvh + (size_t)(3 * p + 0) * TOKD;
        const __half* k = qkvh + (size_t)(3 * p + 1) * TOKD;
        const __half* v = qkvh + (size_t)(3 * p + 2) * TOKD;
        __half* ao = ao4h + (size_t)p * TOKD;
        if (p == 1 || p == 2)
            attn_sparse_k<<<gSparse, 128>>>(q, k, v, ao, p);
        else
            attn_tc_k<<<gAttn, 256, ATT_SMEM_BYTES>>>(q, k, v, ao, p);
    }

    // 5. fused gate+scale+concat, then one K=4096 GEMM through stacked Wo
    gatescale_k<<<TOK, 256>>>(ao4h, weff, fus_bg, gsc);
    dim3 gFuse(Dc / 128, TOK / 128, 1);
    gemm_tc<<<gFuse, 256, GEMM_SMEM>>>(gsc, 0, wos, 0,
                                       nullptr, fusedh, 0, TOK, Dc, 4 * Dc,
                                       nullptr, nullptr, 0);

    // 6. fus_wo projection + first residual (g_m at 2D)
    dim3 gProj(Dc / 128, TOK / 128, 1);
    gemm_tc<<<gProj, 256, GEMM_SMEM>>>(fusedh, 0, wh + WFUS, 0, xmid, nullptr, 0,
                                       TOK, Dc, Dc, x, ada + 2 * Dc, 0);

    // 7. FFN: up-proj with fused SwiGLU epilogue, then down-proj
    ln_mod_k<<<TOK, 256>>>(xmid, ln2_g, ln2_b, ada, 3 * Dc, 4 * Dc, nxh);
    dim3 gUp(8192 / 128, TOK / 128, 1);
    gemm_tc<<<gUp, 256, GEMM_SMEM>>>(nxh, 0, wud, 0,
                                     nullptr, h1h, 0, TOK, 8192, Dc,
                                     nullptr, nullptr, 1);
    gemm_tc<<<gProj, 256, GEMM_SMEM>>>(h1h, 0, wh + W2, 0, out, nullptr, 0,
                                       TOK, Dc, Fc, xmid, ada + 5 * Dc, 0);
}